// round 10
// baseline (speedup 1.0000x reference)
#include <cuda_runtime.h>
#include <cuda_bf16.h>
#include <math.h>
#include <stdint.h>

#define BB 4
#define TT 2048
#define HH 16
#define DD 64
#define CC (HH*DD)      // 1024
#define MM (BB*TT)      // 8192
#define GK 1024         // K of all GEMMs

// ---------------- scratch (device globals; no allocation allowed) ----------
__device__ __align__(256) float g_cos[TT * 32];
__device__ __align__(256) float g_sin[TT * 32];

__device__ __align__(256) __nv_bfloat16 g_xh[(size_t)MM * GK];
__device__ __align__(256) __nv_bfloat16 g_xl[(size_t)MM * GK];
__device__ __align__(256) __nv_bfloat16 g_yh[(size_t)MM * GK];
__device__ __align__(256) __nv_bfloat16 g_yl[(size_t)MM * GK];
__device__ __align__(256) __nv_bfloat16 g_qh[(size_t)BB*HH*TT*DD];
__device__ __align__(256) __nv_bfloat16 g_ql[(size_t)BB*HH*TT*DD];
__device__ __align__(256) __nv_bfloat16 g_kh[(size_t)BB*HH*TT*DD];
__device__ __align__(256) __nv_bfloat16 g_kl[(size_t)BB*HH*TT*DD];
__device__ __align__(256) __nv_bfloat16 g_vth[(size_t)BB*HH*TT*DD];
__device__ __align__(256) __nv_bfloat16 g_vtl[(size_t)BB*HH*TT*DD];
__device__ __align__(256) __nv_bfloat16 g_wh[(size_t)3 * CC * GK];
__device__ __align__(256) __nv_bfloat16 g_wl[(size_t)3 * CC * GK];
__device__ __align__(256) __nv_bfloat16 g_wch[(size_t)CC * GK];
__device__ __align__(256) __nv_bfloat16 g_wcl[(size_t)CC * GK];

// ---------------- helpers ----------------------------------------------------
__device__ __forceinline__ uint32_t smem_u32(const void* p) {
    return (uint32_t)__cvta_generic_to_shared(p);
}

__device__ __forceinline__ void cp_async16(uint32_t saddr, const void* gaddr) {
    asm volatile("cp.async.cg.shared.global [%0], [%1], 16;" :: "r"(saddr), "l"(gaddr) : "memory");
}

__device__ __forceinline__ void ldsm_x4(uint32_t& r0, uint32_t& r1, uint32_t& r2, uint32_t& r3,
                                        uint32_t addr) {
    asm volatile("ldmatrix.sync.aligned.m8n8.x4.shared.b16 {%0,%1,%2,%3}, [%4];"
                 : "=r"(r0), "=r"(r1), "=r"(r2), "=r"(r3) : "r"(addr));
}

__device__ __forceinline__ void mma16816(float& c0, float& c1, float& c2, float& c3,
                                         uint32_t a0, uint32_t a1, uint32_t a2, uint32_t a3,
                                         uint32_t b0, uint32_t b1) {
    asm volatile(
        "mma.sync.aligned.m16n8k16.row.col.f32.bf16.bf16.f32 "
        "{%0,%1,%2,%3}, {%4,%5,%6,%7}, {%8,%9}, {%0,%1,%2,%3};"
        : "+f"(c0), "+f"(c1), "+f"(c2), "+f"(c3)
        : "r"(a0), "r"(a1), "r"(a2), "r"(a3), "r"(b0), "r"(b1));
}

__device__ __forceinline__ uint32_t pack_bf16(float a, float b) {
    __nv_bfloat162 t = __float22bfloat162_rn(make_float2(a, b));
    return *reinterpret_cast<uint32_t*>(&t);
}

__device__ __forceinline__ void store_hl(__nv_bfloat16* hi, __nv_bfloat16* lo,
                                         size_t off, float a, float b) {
    __nv_bfloat162 h = __float22bfloat162_rn(make_float2(a, b));
    float ra = a - __bfloat162float(h.x);
    float rb = b - __bfloat162float(h.y);
    __nv_bfloat162 l = __float22bfloat162_rn(make_float2(ra, rb));
    *reinterpret_cast<__nv_bfloat162*>(hi + off) = h;
    *reinterpret_cast<__nv_bfloat162*>(lo + off) = l;
}

// ---------------- HMMA GEMM: C = (Ah+Al) @ (Bh+Bl)^T -----------------------
// 128x128 CTA tile, 8 warps (2m x 4n), warp tile 64x32, 3-stage cp.async
// pipeline with ONE barrier per k-chunk, XOR-swizzled 64B rows, 2 CTAs/SM.
#define BK 32
#define NUMK (GK / BK)          // 32
#define ROWB 64                 // 64B data, swizzled (no pad)
#define TILE_B (128 * ROWB)     // 8192
#define STAGE_B (4 * TILE_B)    // 32768
#define SMEM_DYN (3 * STAGE_B)  // 98304 -> 2 CTAs/SM

__global__ void __launch_bounds__(256, 2)
gemm_kernel_mma(const __nv_bfloat16* __restrict__ Ah, const __nv_bfloat16* __restrict__ Al,
                const __nv_bfloat16* __restrict__ Bh, const __nv_bfloat16* __restrict__ Bl,
                float* __restrict__ Cm, int Ndim, int mode,
                const float* __restrict__ gcos, const float* __restrict__ gsin,
                __nv_bfloat16* __restrict__ qh, __nv_bfloat16* __restrict__ ql,
                __nv_bfloat16* __restrict__ kh, __nv_bfloat16* __restrict__ kl,
                __nv_bfloat16* __restrict__ vth, __nv_bfloat16* __restrict__ vtl)
{
    extern __shared__ char smem_raw[];
    const uint32_t sbase = smem_u32(smem_raw);

    const int tid  = threadIdx.x;
    const int lane = tid & 31;
    const int warp = tid >> 5;
    const int mw   = warp & 1;
    const int nw   = warp >> 1;
    const int m0 = blockIdx.y * 128;
    const int n0 = blockIdx.x * 128;

    const __nv_bfloat16* tp[4] = { Ah, Al, Bh, Bl };

    auto prefetch = [&](int kc) {
        const uint32_t sstage = sbase + (uint32_t)(kc % 3) * STAGE_B;
        #pragma unroll
        for (int i = 0; i < 8; i++) {
            const int c = i * 256 + tid;
            const int tile = c >> 9;
            const int r = (c >> 2) & 127;
            const int j = c & 3;
            const int row0 = (tile < 2) ? m0 : n0;
            const __nv_bfloat16* g = tp[tile] + (size_t)(row0 + r) * GK + kc * BK + j * 8;
            cp_async16(sstage + tile * TILE_B + r * ROWB + ((j ^ ((r >> 1) & 3)) << 4), g);
        }
    };

    prefetch(0);
    asm volatile("cp.async.commit_group;" ::: "memory");
    prefetch(1);
    asm volatile("cp.async.commit_group;" ::: "memory");

    const uint32_t aRowBase = (uint32_t)((mw * 64 + (lane & 15)) * ROWB);
    const uint32_t xa = ((lane & 15) >> 1) & 3;
    const uint32_t bRowBase = (uint32_t)((nw * 32 + (lane & 7) + ((lane >> 4) << 3)) * ROWB);
    const uint32_t xb = ((lane & 7) >> 1) & 3;
    const uint32_t aHalf = (lane >> 4);
    const uint32_t bHalf = ((lane >> 3) & 1);

    float acc[4][4][4];
    #pragma unroll
    for (int mt = 0; mt < 4; mt++)
        #pragma unroll
        for (int nt = 0; nt < 4; nt++)
            #pragma unroll
            for (int e = 0; e < 4; e++) acc[mt][nt][e] = 0.f;

    for (int kc = 0; kc < NUMK; kc++) {
        asm volatile("cp.async.wait_group 1;" ::: "memory");
        __syncthreads();

        const uint32_t sstage = sbase + (uint32_t)(kc % 3) * STAGE_B;
        const uint32_t aTile = sstage;
        const uint32_t bTile = sstage + 2 * TILE_B;

        #pragma unroll
        for (int ks = 0; ks < 2; ks++) {
            const uint32_t aOff = ((uint32_t)(ks * 2 + aHalf) ^ xa) << 4;
            const uint32_t bOff = ((uint32_t)(ks * 2 + bHalf) ^ xb) << 4;
            uint32_t bh[4][2], bl[4][2];
            #pragma unroll
            for (int np = 0; np < 2; np++) {
                const uint32_t off = bRowBase + np * (16 * ROWB) + bOff;
                ldsm_x4(bh[np*2][0], bh[np*2][1], bh[np*2+1][0], bh[np*2+1][1], bTile + off);
                ldsm_x4(bl[np*2][0], bl[np*2][1], bl[np*2+1][0], bl[np*2+1][1],
                        bTile + TILE_B + off);
            }
            #pragma unroll
            for (int mt = 0; mt < 4; mt++) {
                uint32_t ah[4], al[4];
                const uint32_t off = aRowBase + mt * (16 * ROWB) + aOff;
                ldsm_x4(ah[0], ah[1], ah[2], ah[3], aTile + off);
                ldsm_x4(al[0], al[1], al[2], al[3], aTile + TILE_B + off);
                #pragma unroll
                for (int nt = 0; nt < 4; nt++) {
                    float* c = acc[mt][nt];
                    mma16816(c[0], c[1], c[2], c[3],
                             ah[0], ah[1], ah[2], ah[3], bh[nt][0], bh[nt][1]);
                    mma16816(c[0], c[1], c[2], c[3],
                             ah[0], ah[1], ah[2], ah[3], bl[nt][0], bl[nt][1]);
                    mma16816(c[0], c[1], c[2], c[3],
                             al[0], al[1], al[2], al[3], bh[nt][0], bh[nt][1]);
                }
            }
        }
        if (kc + 2 < NUMK) prefetch(kc + 2);
        asm volatile("cp.async.commit_group;" ::: "memory");
    }

    if (mode == 0) {
        const int rbase = m0 + mw * 64 + (lane >> 2);
        const int cbase = n0 + nw * 32 + ((lane & 3) << 1);
        #pragma unroll
        for (int mt = 0; mt < 4; mt++) {
            #pragma unroll
            for (int nt = 0; nt < 4; nt++) {
                float* c = acc[mt][nt];
                float* p0 = Cm + (size_t)(rbase + mt * 16) * Ndim + cbase + nt * 8;
                float* p1 = p0 + (size_t)8 * Ndim;
                *reinterpret_cast<float2*>(p0) = make_float2(c[0], c[1]);
                *reinterpret_cast<float2*>(p1) = make_float2(c[2], c[3]);
            }
        }
        return;
    }

    // ---- fused QKV epilogue: stage fp32 tile in smem [128][132] ----
    float* sm = reinterpret_cast<float*>(smem_raw);
    __syncthreads();
    const int rloc = mw * 64 + (lane >> 2);
    const int cloc = nw * 32 + ((lane & 3) << 1);
    #pragma unroll
    for (int mt = 0; mt < 4; mt++) {
        #pragma unroll
        for (int nt = 0; nt < 4; nt++) {
            float* c = acc[mt][nt];
            float* p0 = sm + (size_t)(rloc + mt * 16) * 132 + cloc + nt * 8;
            *reinterpret_cast<float2*>(p0)           = make_float2(c[0], c[1]);
            *reinterpret_cast<float2*>(p0 + 8 * 132) = make_float2(c[2], c[3]);
        }
    }
    __syncthreads();

    const int ct = blockIdx.x;
    const int b = m0 >> 11;
    const int t_base = m0 & (TT - 1);

    if (ct < 16) {
        const bool isQ = (ct < 8);
        const float qs = isQ ? 0.125f : 1.0f;
        __nv_bfloat16* dh = isQ ? qh : kh;
        __nv_bfloat16* dl = isQ ? ql : kl;
        const int hbase = (isQ ? ct : (ct - 8)) * 2;
        #pragma unroll
        for (int i = 0; i < 16; i++) {
            const int idx = i * 256 + tid;
            const int dp = (idx & 15) * 2;
            const int hs = (idx >> 4) & 1;
            const int r  = idx >> 5;
            const int t  = t_base + r;
            const float c0 = gcos[t * 32 + dp],  c1 = gcos[t * 32 + dp + 1];
            const float s0 = gsin[t * 32 + dp],  s1 = gsin[t * 32 + dp + 1];
            const float* row = sm + (size_t)r * 132 + hs * 64;
            const float x1 = row[dp],      x1b = row[dp + 1];
            const float x2 = row[dp + 32], x2b = row[dp + 33];
            const float o0 = (x1 * c0 - x2 * s0) * qs;
            const float o1 = (x1b * c1 - x2b * s1) * qs;
            const float o2 = (x2 * c0 + x1 * s0) * qs;
            const float o3 = (x2b * c1 + x1b * s1) * qs;
            const size_t base = (((size_t)b * HH + hbase + hs) * TT + t) * 64;
            store_hl(dh, dl, base + dp, o0, o1);
            store_hl(dh, dl, base + dp + 32, o2, o3);
        }
    } else {
        const int hbase = (ct - 16) * 2;
        #pragma unroll
        for (int i = 0; i < 32; i++) {
            const int idx = i * 256 + tid;
            const int c  = idx >> 6;
            const int t2 = idx & 63;
            const int hs = c >> 6;
            const int d  = c & 63;
            const float a  = sm[(size_t)(2 * t2) * 132 + c];
            const float bv = sm[(size_t)(2 * t2 + 1) * 132 + c];
            const int t = t_base + 2 * t2;
            store_hl(vth, vtl,
                     (((size_t)b * HH + hbase + hs) * 64 + d) * TT + t, a, bv);
        }
    }
}

// ---------------- fp32 -> bf16 hi/lo split ---------------------------------
__global__ void split_kernel(const float4* __restrict__ in,
                             uint2* __restrict__ hi, uint2* __restrict__ lo, int n4)
{
    int i = blockIdx.x * blockDim.x + threadIdx.x;
    if (i >= n4) return;
    float4 v = in[i];
    float vv[4] = { v.x, v.y, v.z, v.w };
    unsigned short h[4], l[4];
    #pragma unroll
    for (int k = 0; k < 4; k++) {
        __nv_bfloat16 hb = __float2bfloat16(vv[k]);
        __nv_bfloat16 lb = __float2bfloat16(vv[k] - __bfloat162float(hb));
        h[k] = __bfloat16_as_ushort(hb);
        l[k] = __bfloat16_as_ushort(lb);
    }
    uint2 ho, lo_;
    ho.x = (uint32_t)h[0] | ((uint32_t)h[1] << 16);
    ho.y = (uint32_t)h[2] | ((uint32_t)h[3] << 16);
    lo_.x = (uint32_t)l[0] | ((uint32_t)l[1] << 16);
    lo_.y = (uint32_t)l[2] | ((uint32_t)l[3] << 16);
    hi[i] = ho;
    lo[i] = lo_;
}

// -------- combined W transpose-split + RoPE table, ONE launch --------------
__global__ void transpose_split_all(const float* __restrict__ Wq,
                                    const float* __restrict__ Wkv,
                                    const float* __restrict__ Wc,
                                    __nv_bfloat16* __restrict__ wh,
                                    __nv_bfloat16* __restrict__ wl,
                                    __nv_bfloat16* __restrict__ wch,
                                    __nv_bfloat16* __restrict__ wcl,
                                    float* __restrict__ gcos, float* __restrict__ gsin)
{
    const int tx = threadIdx.x, ty = threadIdx.y;
    if (blockIdx.y == 32) {
        const int tid = ty * 32 + tx;
        #pragma unroll
        for (int e = 0; e < 2; e++) {
            int i = blockIdx.x * 512 + e * 256 + tid;
            int t = i >> 5;
            int d = i & 31;
            float inv = (float)exp(-((double)(2 * d) / 64.0) * log(10000.0));
            float ang = (float)t * inv;
            gcos[i] = cosf(ang);
            gsin[i] = sinf(ang);
        }
        return;
    }

    __shared__ float t[32][33];
    const int nx = blockIdx.x;
    const int k0 = blockIdx.y * 32;
    const float* W;
    __nv_bfloat16 *Th, *Tl;
    int N, n0;
    if (nx < 32)       { W = Wq;  N = CC;     n0 = nx * 32;        Th = wh;  Tl = wl; }
    else if (nx < 96)  { W = Wkv; N = 2 * CC; n0 = (nx - 32) * 32;
                         Th = wh + (size_t)CC * GK; Tl = wl + (size_t)CC * GK; }
    else               { W = Wc;  N = CC;     n0 = (nx - 96) * 32; Th = wch; Tl = wcl; }

    #pragma unroll
    for (int i = 0; i < 32; i += 8)
        t[ty + i][tx] = W[(size_t)(k0 + ty + i) * N + n0 + tx];
    __syncthreads();
    #pragma unroll
    for (int i = 0; i < 32; i += 8) {
        float v = t[tx][ty + i];
        __nv_bfloat16 hb = __float2bfloat16(v);
        size_t o = (size_t)(n0 + ty + i) * GK + k0 + tx;
        Th[o] = hb;
        Tl[o] = __float2bfloat16(v - __bfloat162float(hb));
    }
}

// ---------------- Flash attention on HMMA (bf16 hi/lo, fp32 accum) --------
// 128 threads / 4 warps / 64 q-rows per CTA; KV tiles of 32 rows; 4-stage
// cp.async pipeline, single barrier per tile; 2 CTAs/SM.
#define FQROWB 144                      // Q/K rows: 128B data + 16 pad
#define FVROWB 80                       // V rows: 64B data + 16 pad
#define FQ_TILE (64 * FQROWB)           // 9216 (per hi/lo array)
#define FK_TILE (32 * FQROWB)           // 4608
#define FV_TILE (64 * FVROWB)           // 5120
#define FSTAGE (2 * FK_TILE + 2 * FV_TILE)   // 19456
#define FNST 4
#define FSMEM (2 * FQ_TILE + FNST * FSTAGE)  // 96256 -> 2 CTAs/SM

__global__ void __launch_bounds__(128, 2)
flash_mma_kernel(const __nv_bfloat16* __restrict__ qh, const __nv_bfloat16* __restrict__ ql,
                 const __nv_bfloat16* __restrict__ kh, const __nv_bfloat16* __restrict__ kl,
                 const __nv_bfloat16* __restrict__ vth, const __nv_bfloat16* __restrict__ vtl,
                 __nv_bfloat16* __restrict__ yh, __nv_bfloat16* __restrict__ yl)
{
    extern __shared__ char smem_raw[];
    const uint32_t sQ  = smem_u32(smem_raw);
    const uint32_t sKV = sQ + 2 * FQ_TILE;

    const int tid = threadIdx.x, lane = tid & 31, warp = tid >> 5;
    const int t0 = (gridDim.x - 1 - blockIdx.x) * 64;    // heavy-first
    const int h = blockIdx.y, b = blockIdx.z;
    const size_t bh = (size_t)b * HH + h;
    const int nkv = t0 / 32 + 2;

    // Q prefetch: 2 arrays x 64 rows x 8 chunks = 1024 / 128thr = 8 each
    #pragma unroll
    for (int i = 0; i < 8; i++) {
        int idx = i * 128 + tid;
        int arr = idx >> 9, r = (idx >> 3) & 63, j = idx & 7;
        const __nv_bfloat16* g = (arr ? ql : qh) + (bh * TT + t0 + r) * 64 + j * 8;
        cp_async16(sQ + arr * FQ_TILE + r * FQROWB + j * 16, g);
    }
    // KV prefetch: K 32r x 8c x2 + V 64r x 4c x2 = 1024 / 128thr = 8 each
    auto pref_kv = [&](int n) {
        const uint32_t sb = sKV + (uint32_t)(n % FNST) * FSTAGE;
        const int j0 = n * 32;
        #pragma unroll
        for (int i = 0; i < 8; i++) {
            int idx = i * 128 + tid;
            int arr = idx >> 8;                 // 0=kh 1=kl 2=vth 3=vtl
            if (arr < 2) {
                int r = (idx >> 3) & 31, j = idx & 7;
                const __nv_bfloat16* g = (arr ? kl : kh) + (bh * TT + j0 + r) * 64 + j * 8;
                cp_async16(sb + arr * FK_TILE + r * FQROWB + j * 16, g);
            } else {
                int r = (idx >> 2) & 63, j = idx & 3;
                const __nv_bfloat16* g = ((arr == 3) ? vtl : vth) + (bh * 64 + r) * TT + j0 + j * 8;
                cp_async16(sb + 2 * FK_TILE + (arr - 2) * FV_TILE + r * FVROWB + j * 16, g);
            }
        }
    };
    pref_kv(0);
    asm volatile("cp.async.commit_group;" ::: "memory");
    pref_kv(1);
    asm volatile("cp.async.commit_group;" ::: "memory");
    pref_kv(2);
    asm volatile("cp.async.commit_group;" ::: "memory");

    const int wrow = t0 + warp * 16;
    const int gr = lane >> 2;
    const int qk = (lane & 3) * 2;
    const int row0 = wrow + gr;
    const int row1 = row0 + 8;

    uint32_t qa_h[4][4], qa_l[4][4];
    float O[8][4];
    #pragma unroll
    for (int nt = 0; nt < 8; nt++)
        #pragma unroll
        for (int e = 0; e < 4; e++) O[nt][e] = 0.f;
    float mA = -1e30f, mB = -1e30f, lA = 0.f, lB = 0.f;

    const uint32_t bRow  = (lane & 7) + ((lane >> 4) << 3);
    const uint32_t bHalf = ((lane >> 3) & 1) << 4;
    const uint32_t kBase = bRow * FQROWB + bHalf;
    const uint32_t vBase = bRow * FVROWB + bHalf;

    for (int n = 0; n < nkv; n++) {
        asm volatile("cp.async.wait_group 2;" ::: "memory");
        __syncthreads();   // single barrier; 4-stage overwrite safety

        if (n == 0) {
            const uint32_t qb = sQ + (warp * 16 + (lane & 15)) * FQROWB + ((lane >> 4) << 4);
            #pragma unroll
            for (int ks = 0; ks < 4; ks++) {
                ldsm_x4(qa_h[ks][0], qa_h[ks][1], qa_h[ks][2], qa_h[ks][3], qb + ks * 32);
                ldsm_x4(qa_l[ks][0], qa_l[ks][1], qa_l[ks][2], qa_l[ks][3],
                        qb + FQ_TILE + ks * 32);
            }
        }

        const int j0 = n * 32;
        if (j0 <= wrow + 15) {
            const uint32_t sb = sKV + (uint32_t)(n % FNST) * FSTAGE;
            float S[4][4];
            #pragma unroll
            for (int nt = 0; nt < 4; nt++)
                #pragma unroll
                for (int e = 0; e < 4; e++) S[nt][e] = 0.f;

            // ---- S = Q K^T (3-product split), 4 n8-tiles over 32 kv rows ----
            #pragma unroll
            for (int ks = 0; ks < 4; ks++) {
                uint32_t B0h[4], B1h[4], B0l[4], B1l[4];
                #pragma unroll
                for (int np = 0; np < 2; np++) {
                    const uint32_t off = kBase + np * (16 * FQROWB) + ks * 32;
                    ldsm_x4(B0h[np*2], B1h[np*2], B0h[np*2+1], B1h[np*2+1], sb + off);
                    ldsm_x4(B0l[np*2], B1l[np*2], B0l[np*2+1], B1l[np*2+1],
                            sb + FK_TILE + off);
                }
                #pragma unroll
                for (int nt = 0; nt < 4; nt++) {
                    float* c = S[nt];
                    mma16816(c[0], c[1], c[2], c[3],
                             qa_h[ks][0], qa_h[ks][1], qa_h[ks][2], qa_h[ks][3],
                             B0h[nt], B1h[nt]);
                    mma16816(c[0], c[1], c[2], c[3],
                             qa_h[ks][0], qa_h[ks][1], qa_h[ks][2], qa_h[ks][3],
                             B0l[nt], B1l[nt]);
                    mma16816(c[0], c[1], c[2], c[3],
                             qa_l[ks][0], qa_l[ks][1], qa_l[ks][2], qa_l[ks][3],
                             B0h[nt], B1h[nt]);
                }
            }

            // ---- causal mask ----
            if (j0 + 31 > wrow) {
                #pragma unroll
                for (int nt = 0; nt < 4; nt++) {
                    const int c0 = j0 + nt * 8 + qk;
                    if (c0 > row0)     S[nt][0] = -1e30f;
                    if (c0 + 1 > row0) S[nt][1] = -1e30f;
                    if (c0 > row1)     S[nt][2] = -1e30f;
                    if (c0 + 1 > row1) S[nt][3] = -1e30f;
                }
            }

            // ---- online softmax ----
            float tmA = -1e30f, tmB = -1e30f;
            #pragma unroll
            for (int nt = 0; nt < 4; nt++) {
                tmA = fmaxf(tmA, fmaxf(S[nt][0], S[nt][1]));
                tmB = fmaxf(tmB, fmaxf(S[nt][2], S[nt][3]));
            }
            tmA = fmaxf(tmA, __shfl_xor_sync(0xffffffffu, tmA, 1));
            tmA = fmaxf(tmA, __shfl_xor_sync(0xffffffffu, tmA, 2));
            tmB = fmaxf(tmB, __shfl_xor_sync(0xffffffffu, tmB, 1));
            tmB = fmaxf(tmB, __shfl_xor_sync(0xffffffffu, tmB, 2));
            const float mnA = fmaxf(mA, tmA), mnB = fmaxf(mB, tmB);
            const float aA = __expf(mA - mnA), aB = __expf(mB - mnB);
            float sumA = 0.f, sumB = 0.f;
            #pragma unroll
            for (int nt = 0; nt < 4; nt++) {
                S[nt][0] = __expf(S[nt][0] - mnA);
                S[nt][1] = __expf(S[nt][1] - mnA);
                S[nt][2] = __expf(S[nt][2] - mnB);
                S[nt][3] = __expf(S[nt][3] - mnB);
                sumA += S[nt][0] + S[nt][1];
                sumB += S[nt][2] + S[nt][3];
            }
            sumA += __shfl_xor_sync(0xffffffffu, sumA, 1);
            sumA += __shfl_xor_sync(0xffffffffu, sumA, 2);
            sumB += __shfl_xor_sync(0xffffffffu, sumB, 1);
            sumB += __shfl_xor_sync(0xffffffffu, sumB, 2);
            lA = lA * aA + sumA;
            lB = lB * aB + sumB;
            mA = mnA; mB = mnB;
            #pragma unroll
            for (int nt = 0; nt < 8; nt++) {
                O[nt][0] *= aA; O[nt][1] *= aA;
                O[nt][2] *= aB; O[nt][3] *= aB;
            }

            // ---- O += P V (3-product split), k = 32 -> 2 ks steps ----
            const uint32_t vb = sb + 2 * FK_TILE;
            #pragma unroll
            for (int ks = 0; ks < 2; ks++) {
                const int n0t = 2 * ks, n1t = 2 * ks + 1;
                uint32_t pah[4], pal[4];
                {
                    __nv_bfloat162 h0 = __float22bfloat162_rn(make_float2(S[n0t][0], S[n0t][1]));
                    __nv_bfloat162 h1 = __float22bfloat162_rn(make_float2(S[n0t][2], S[n0t][3]));
                    __nv_bfloat162 h2 = __float22bfloat162_rn(make_float2(S[n1t][0], S[n1t][1]));
                    __nv_bfloat162 h3 = __float22bfloat162_rn(make_float2(S[n1t][2], S[n1t][3]));
                    pah[0] = *reinterpret_cast<uint32_t*>(&h0);
                    pah[1] = *reinterpret_cast<uint32_t*>(&h1);
                    pah[2] = *reinterpret_cast<uint32_t*>(&h2);
                    pah[3] = *reinterpret_cast<uint32_t*>(&h3);
                    pal[0] = pack_bf16(S[n0t][0] - __bfloat162float(h0.x),
                                       S[n0t][1] - __bfloat162float(h0.y));
                    pal[1] = pack_bf16(S[n0t][2] - __bfloat162float(h1.x),
                                       S[n0t][3] - __bfloat162float(h1.y));
                    pal[2] = pack_bf16(S[n1t][0] - __bfloat162float(h2.x),
                                       S[n1t][1] - __bfloat162float(h2.y));
                    pal[3] = pack_bf16(S[n1t][2] - __bfloat162float(h3.x),
                                       S[n1t][3] - __bfloat162float(h3.y));
                }
                uint32_t V0h[8], V1h[8], V0l[8], V1l[8];
                #pragma unroll
                for (int q2 = 0; q2 < 4; q2++) {
                    const uint32_t off = vBase + q2 * (16 * FVROWB) + ks * 32;
                    ldsm_x4(V0h[q2*2], V1h[q2*2], V0h[q2*2+1], V1h[q2*2+1], vb + off);
                    ldsm_x4(V0l[q2*2], V1l[q2*2], V0l[q2*2+1], V1l[q2*2+1],
                            vb + FV_TILE + off);
                }
                #pragma unroll
                for (int nt = 0; nt < 8; nt++) {
                    float* c = O[nt];
                    mma16816(c[0], c[1], c[2], c[3],
                             pah[0], pah[1], pah[2], pah[3], V0h[nt], V1h[nt]);
                    mma16816(c[0], c[1], c[2], c[3],
                             pah[0], pah[1], pah[2], pah[3], V0l[nt], V1l[nt]);
                    mma16816(c[0], c[1], c[2], c[3],
                             pal[0], pal[1], pal[2], pal[3], V0h[nt], V1h[nt]);
                }
            }
        }
        if (n + 3 < nkv) pref_kv(n + 3);
        asm volatile("cp.async.commit_group;" ::: "memory");
    }

    const float iA = 1.f / lA, iB = 1.f / lB;
    #pragma unroll
    for (int nt = 0; nt < 8; nt++) {
        const size_t d0 = (size_t)h * 64 + nt * 8 + qk;
        store_hl(yh, yl, ((size_t)b * TT + row0) * CC + d0, O[nt][0] * iA, O[nt][1] * iA);
        store_hl(yh, yl, ((size_t)b * TT + row1) * CC + d0, O[nt][2] * iB, O[nt][3] * iB);
    }
}

// ---------------- launch ---------------------------------------------------
extern "C" void kernel_launch(void* const* d_in, const int* in_sizes, int n_in,
                              void* d_out, int out_size)
{
    const float* x   = (const float*)d_in[0];
    const float* Wq  = (const float*)d_in[1];
    const float* Wkv = (const float*)d_in[2];
    const float* Wc  = (const float*)d_in[3];
    float* out = (float*)d_out;

    float *gc, *gs;
    __nv_bfloat16 *xh, *xl, *yh, *yl, *wh, *wl, *wch, *wcl;
    __nv_bfloat16 *qh, *ql, *kh, *kl, *vth, *vtl;
    cudaGetSymbolAddress((void**)&gc, g_cos);
    cudaGetSymbolAddress((void**)&gs, g_sin);
    cudaGetSymbolAddress((void**)&xh, g_xh);
    cudaGetSymbolAddress((void**)&xl, g_xl);
    cudaGetSymbolAddress((void**)&yh, g_yh);
    cudaGetSymbolAddress((void**)&yl, g_yl);
    cudaGetSymbolAddress((void**)&wh, g_wh);
    cudaGetSymbolAddress((void**)&wl, g_wl);
    cudaGetSymbolAddress((void**)&wch, g_wch);
    cudaGetSymbolAddress((void**)&wcl, g_wcl);
    cudaGetSymbolAddress((void**)&qh, g_qh);
    cudaGetSymbolAddress((void**)&ql, g_ql);
    cudaGetSymbolAddress((void**)&kh, g_kh);
    cudaGetSymbolAddress((void**)&kl, g_kl);
    cudaGetSymbolAddress((void**)&vth, g_vth);
    cudaGetSymbolAddress((void**)&vtl, g_vtl);

    cudaFuncSetAttribute(gemm_kernel_mma, cudaFuncAttributeMaxDynamicSharedMemorySize, SMEM_DYN);
    cudaFuncSetAttribute(flash_mma_kernel, cudaFuncAttributeMaxDynamicSharedMemorySize, FSMEM);

    // #0: split x
    {
        int n4 = MM * GK / 4;
        split_kernel<<<(n4 + 255) / 256, 256>>>((const float4*)x, (uint2*)xh, (uint2*)xl, n4);
    }
    // #1: all weight transposes + rope table
    transpose_split_all<<<dim3(128, GK / 32 + 1), dim3(32, 8)>>>(
        Wq, Wkv, Wc, wh, wl, wch, wcl, gc, gs);

    // #2: fused QKV GEMM
    gemm_kernel_mma<<<dim3(3 * CC / 128, MM / 128), 256, SMEM_DYN>>>(
        xh, xl, wh, wl, nullptr, 3 * CC, 1, gc, gs, qh, ql, kh, kl, vth, vtl);

    // #3: attention (ncu target)
    flash_mma_kernel<<<dim3(TT / 64, HH, BB), 128, FSMEM>>>(qh, ql, kh, kl, vth, vtl, yh, yl);

    // #4: out = y @ Wc
    gemm_kernel_mma<<<dim3(CC / 128, MM / 128), 256, SMEM_DYN>>>(
        yh, yl, wch, wcl, out, CC, 0, nullptr, nullptr,
        nullptr, nullptr, nullptr, nullptr, nullptr, nullptr);
}

// round 11
// speedup vs baseline: 1.5957x; 1.5957x over previous
#include <cuda_runtime.h>
#include <cuda_fp16.h>
#include <math.h>
#include <stdint.h>

#define BB 4
#define TT 2048
#define HH 16
#define DD 64
#define CC (HH*DD)      // 1024
#define MM (BB*TT)      // 8192
#define GK 1024         // K of all GEMMs

// ---------------- scratch (device globals; no allocation allowed) ----------
__device__ __align__(256) float g_cos[TT * 32];
__device__ __align__(256) float g_sin[TT * 32];

__device__ __align__(256) __half g_x16[(size_t)MM * GK];
__device__ __align__(256) __half g_y16[(size_t)MM * GK];
__device__ __align__(256) __half g_q16[(size_t)BB*HH*TT*DD];
__device__ __align__(256) __half g_k16[(size_t)BB*HH*TT*DD];
__device__ __align__(256) __half g_vt16[(size_t)BB*HH*TT*DD];
// weights transposed [N,K], fp16 hi + lo
__device__ __align__(256) __half g_wh[(size_t)3 * CC * GK];
__device__ __align__(256) __half g_wl[(size_t)3 * CC * GK];
__device__ __align__(256) __half g_wch[(size_t)CC * GK];
__device__ __align__(256) __half g_wcl[(size_t)CC * GK];

// ---------------- helpers ----------------------------------------------------
__device__ __forceinline__ uint32_t smem_u32(const void* p) {
    return (uint32_t)__cvta_generic_to_shared(p);
}

__device__ __forceinline__ void cp_async16(uint32_t saddr, const void* gaddr) {
    asm volatile("cp.async.cg.shared.global [%0], [%1], 16;" :: "r"(saddr), "l"(gaddr) : "memory");
}

__device__ __forceinline__ void ldsm_x4(uint32_t& r0, uint32_t& r1, uint32_t& r2, uint32_t& r3,
                                        uint32_t addr) {
    asm volatile("ldmatrix.sync.aligned.m8n8.x4.shared.b16 {%0,%1,%2,%3}, [%4];"
                 : "=r"(r0), "=r"(r1), "=r"(r2), "=r"(r3) : "r"(addr));
}

__device__ __forceinline__ void mma16816(float& c0, float& c1, float& c2, float& c3,
                                         uint32_t a0, uint32_t a1, uint32_t a2, uint32_t a3,
                                         uint32_t b0, uint32_t b1) {
    asm volatile(
        "mma.sync.aligned.m16n8k16.row.col.f32.f16.f16.f32 "
        "{%0,%1,%2,%3}, {%4,%5,%6,%7}, {%8,%9}, {%0,%1,%2,%3};"
        : "+f"(c0), "+f"(c1), "+f"(c2), "+f"(c3)
        : "r"(a0), "r"(a1), "r"(a2), "r"(a3), "r"(b0), "r"(b1));
}

__device__ __forceinline__ uint32_t pack_h16(float a, float b) {
    __half2 t = __floats2half2_rn(a, b);
    return *reinterpret_cast<uint32_t*>(&t);
}

__device__ __forceinline__ void store_h2(__half* dst, size_t off, float a, float b) {
    *reinterpret_cast<__half2*>(dst + off) = __floats2half2_rn(a, b);
}

// ---------------- HMMA GEMM: C = A16 @ (Bh+Bl)^T ---------------------------
// 128x128 CTA tile, 8 warps (2m x 4n), warp tile 64x32, 3-stage cp.async
// pipeline, ONE barrier per k-chunk, XOR-swizzled 64B rows, 2 CTAs/SM.
// A: fp16 (single); B: fp16 hi + lo. 2 MMAs per tile-product.
#define BK 32
#define NUMK (GK / BK)          // 32
#define ROWB 64                 // 64B data (32 fp16), swizzled
#define TILE_B (128 * ROWB)     // 8192
#define STAGE_B (3 * TILE_B)    // 24576 (A, Bh, Bl)
#define SMEM_DYN (3 * STAGE_B)  // 73728 -> 2 CTAs/SM

__global__ void __launch_bounds__(256, 2)
gemm_kernel_mma(const __half* __restrict__ A16,
                const __half* __restrict__ Bh, const __half* __restrict__ Bl,
                float* __restrict__ Cm, int Ndim, int mode,
                const float* __restrict__ gcos, const float* __restrict__ gsin,
                __half* __restrict__ q16, __half* __restrict__ k16,
                __half* __restrict__ vt16)
{
    extern __shared__ char smem_raw[];
    const uint32_t sbase = smem_u32(smem_raw);

    const int tid  = threadIdx.x;
    const int lane = tid & 31;
    const int warp = tid >> 5;
    const int mw   = warp & 1;
    const int nw   = warp >> 1;
    const int m0 = blockIdx.y * 128;
    const int n0 = blockIdx.x * 128;

    auto prefetch = [&](int kc) {
        const uint32_t sstage = sbase + (uint32_t)(kc % 3) * STAGE_B;
        #pragma unroll
        for (int i = 0; i < 6; i++) {
            const int c = i * 256 + tid;        // 0..1535
            const int tile = c >> 9;            // 0=A 1=Bh 2=Bl
            const int r = (c >> 2) & 127;
            const int j = c & 3;
            const __half* g;
            if (tile == 0)      g = A16 + (size_t)(m0 + r) * GK + kc * BK + j * 8;
            else if (tile == 1) g = Bh  + (size_t)(n0 + r) * GK + kc * BK + j * 8;
            else                g = Bl  + (size_t)(n0 + r) * GK + kc * BK + j * 8;
            cp_async16(sstage + tile * TILE_B + r * ROWB + ((j ^ ((r >> 1) & 3)) << 4), g);
        }
    };

    prefetch(0);
    asm volatile("cp.async.commit_group;" ::: "memory");
    prefetch(1);
    asm volatile("cp.async.commit_group;" ::: "memory");

    const uint32_t aRowBase = (uint32_t)((mw * 64 + (lane & 15)) * ROWB);
    const uint32_t xa = ((lane & 15) >> 1) & 3;
    const uint32_t bRowBase = (uint32_t)((nw * 32 + (lane & 7) + ((lane >> 4) << 3)) * ROWB);
    const uint32_t xb = ((lane & 7) >> 1) & 3;
    const uint32_t aHalf = (lane >> 4);
    const uint32_t bHalf = ((lane >> 3) & 1);

    float acc[4][4][4];
    #pragma unroll
    for (int mt = 0; mt < 4; mt++)
        #pragma unroll
        for (int nt = 0; nt < 4; nt++)
            #pragma unroll
            for (int e = 0; e < 4; e++) acc[mt][nt][e] = 0.f;

    for (int kc = 0; kc < NUMK; kc++) {
        asm volatile("cp.async.wait_group 1;" ::: "memory");
        __syncthreads();

        const uint32_t sstage = sbase + (uint32_t)(kc % 3) * STAGE_B;
        const uint32_t aTile  = sstage;
        const uint32_t bTileH = sstage + TILE_B;
        const uint32_t bTileL = sstage + 2 * TILE_B;

        #pragma unroll
        for (int ks = 0; ks < 2; ks++) {
            const uint32_t aOff = ((uint32_t)(ks * 2 + aHalf) ^ xa) << 4;
            const uint32_t bOff = ((uint32_t)(ks * 2 + bHalf) ^ xb) << 4;
            uint32_t bh[4][2], bl[4][2];
            #pragma unroll
            for (int np = 0; np < 2; np++) {
                const uint32_t off = bRowBase + np * (16 * ROWB) + bOff;
                ldsm_x4(bh[np*2][0], bh[np*2][1], bh[np*2+1][0], bh[np*2+1][1], bTileH + off);
                ldsm_x4(bl[np*2][0], bl[np*2][1], bl[np*2+1][0], bl[np*2+1][1], bTileL + off);
            }
            #pragma unroll
            for (int mt = 0; mt < 4; mt++) {
                uint32_t ah[4];
                const uint32_t off = aRowBase + mt * (16 * ROWB) + aOff;
                ldsm_x4(ah[0], ah[1], ah[2], ah[3], aTile + off);
                #pragma unroll
                for (int nt = 0; nt < 4; nt++) {
                    float* c = acc[mt][nt];
                    mma16816(c[0], c[1], c[2], c[3],
                             ah[0], ah[1], ah[2], ah[3], bh[nt][0], bh[nt][1]);
                    mma16816(c[0], c[1], c[2], c[3],
                             ah[0], ah[1], ah[2], ah[3], bl[nt][0], bl[nt][1]);
                }
            }
        }
        if (kc + 2 < NUMK) prefetch(kc + 2);
        asm volatile("cp.async.commit_group;" ::: "memory");
    }

    if (mode == 0) {
        const int rbase = m0 + mw * 64 + (lane >> 2);
        const int cbase = n0 + nw * 32 + ((lane & 3) << 1);
        #pragma unroll
        for (int mt = 0; mt < 4; mt++) {
            #pragma unroll
            for (int nt = 0; nt < 4; nt++) {
                float* c = acc[mt][nt];
                float* p0 = Cm + (size_t)(rbase + mt * 16) * Ndim + cbase + nt * 8;
                float* p1 = p0 + (size_t)8 * Ndim;
                *reinterpret_cast<float2*>(p0) = make_float2(c[0], c[1]);
                *reinterpret_cast<float2*>(p1) = make_float2(c[2], c[3]);
            }
        }
        return;
    }

    // ---- fused QKV epilogue: stage fp32 tile in smem [128][132] ----
    float* sm = reinterpret_cast<float*>(smem_raw);
    __syncthreads();
    const int rloc = mw * 64 + (lane >> 2);
    const int cloc = nw * 32 + ((lane & 3) << 1);
    #pragma unroll
    for (int mt = 0; mt < 4; mt++) {
        #pragma unroll
        for (int nt = 0; nt < 4; nt++) {
            float* c = acc[mt][nt];
            float* p0 = sm + (size_t)(rloc + mt * 16) * 132 + cloc + nt * 8;
            *reinterpret_cast<float2*>(p0)           = make_float2(c[0], c[1]);
            *reinterpret_cast<float2*>(p0 + 8 * 132) = make_float2(c[2], c[3]);
        }
    }
    __syncthreads();

    const int ct = blockIdx.x;
    const int b = m0 >> 11;
    const int t_base = m0 & (TT - 1);

    if (ct < 16) {
        const bool isQ = (ct < 8);
        const float qs = isQ ? 0.125f : 1.0f;
        __half* dst = isQ ? q16 : k16;
        const int hbase = (isQ ? ct : (ct - 8)) * 2;
        #pragma unroll
        for (int i = 0; i < 16; i++) {
            const int idx = i * 256 + tid;
            const int dp = (idx & 15) * 2;
            const int hs = (idx >> 4) & 1;
            const int r  = idx >> 5;
            const int t  = t_base + r;
            const float c0 = gcos[t * 32 + dp],  c1 = gcos[t * 32 + dp + 1];
            const float s0 = gsin[t * 32 + dp],  s1 = gsin[t * 32 + dp + 1];
            const float* row = sm + (size_t)r * 132 + hs * 64;
            const float x1 = row[dp],      x1b = row[dp + 1];
            const float x2 = row[dp + 32], x2b = row[dp + 33];
            const float o0 = (x1 * c0 - x2 * s0) * qs;
            const float o1 = (x1b * c1 - x2b * s1) * qs;
            const float o2 = (x2 * c0 + x1 * s0) * qs;
            const float o3 = (x2b * c1 + x1b * s1) * qs;
            const size_t base = (((size_t)b * HH + hbase + hs) * TT + t) * 64;
            store_h2(dst, base + dp, o0, o1);
            store_h2(dst, base + dp + 32, o2, o3);
        }
    } else {
        const int hbase = (ct - 16) * 2;
        #pragma unroll
        for (int i = 0; i < 32; i++) {
            const int idx = i * 256 + tid;
            const int c  = idx >> 6;
            const int t2 = idx & 63;
            const int hs = c >> 6;
            const int d  = c & 63;
            const float a  = sm[(size_t)(2 * t2) * 132 + c];
            const float bv = sm[(size_t)(2 * t2 + 1) * 132 + c];
            const int t = t_base + 2 * t2;
            store_h2(vt16, (((size_t)b * HH + hbase + hs) * 64 + d) * TT + t, a, bv);
        }
    }
}

// ---------------- fp32 -> fp16 convert -------------------------------------
__global__ void split_kernel(const float4* __restrict__ in, uint2* __restrict__ out, int n4)
{
    int i = blockIdx.x * blockDim.x + threadIdx.x;
    if (i >= n4) return;
    float4 v = in[i];
    __half2 a = __floats2half2_rn(v.x, v.y);
    __half2 b = __floats2half2_rn(v.z, v.w);
    uint2 o;
    o.x = *reinterpret_cast<uint32_t*>(&a);
    o.y = *reinterpret_cast<uint32_t*>(&b);
    out[i] = o;
}

// -------- combined W transpose-split (fp16 hi/lo) + RoPE table -------------
__global__ void transpose_split_all(const float* __restrict__ Wq,
                                    const float* __restrict__ Wkv,
                                    const float* __restrict__ Wc,
                                    __half* __restrict__ wh, __half* __restrict__ wl,
                                    __half* __restrict__ wch, __half* __restrict__ wcl,
                                    float* __restrict__ gcos, float* __restrict__ gsin)
{
    const int tx = threadIdx.x, ty = threadIdx.y;
    if (blockIdx.y == 32) {
        const int tid = ty * 32 + tx;
        #pragma unroll
        for (int e = 0; e < 2; e++) {
            int i = blockIdx.x * 512 + e * 256 + tid;
            int t = i >> 5;
            int d = i & 31;
            float inv = (float)exp(-((double)(2 * d) / 64.0) * log(10000.0));
            float ang = (float)t * inv;
            gcos[i] = cosf(ang);
            gsin[i] = sinf(ang);
        }
        return;
    }

    __shared__ float t[32][33];
    const int nx = blockIdx.x;
    const int k0 = blockIdx.y * 32;
    const float* W;
    __half *Th, *Tl;
    int N, n0;
    if (nx < 32)       { W = Wq;  N = CC;     n0 = nx * 32;        Th = wh;  Tl = wl; }
    else if (nx < 96)  { W = Wkv; N = 2 * CC; n0 = (nx - 32) * 32;
                         Th = wh + (size_t)CC * GK; Tl = wl + (size_t)CC * GK; }
    else               { W = Wc;  N = CC;     n0 = (nx - 96) * 32; Th = wch; Tl = wcl; }

    #pragma unroll
    for (int i = 0; i < 32; i += 8)
        t[ty + i][tx] = W[(size_t)(k0 + ty + i) * N + n0 + tx];
    __syncthreads();
    #pragma unroll
    for (int i = 0; i < 32; i += 8) {
        float v = t[tx][ty + i];
        __half hb = __float2half_rn(v);
        size_t o = (size_t)(n0 + ty + i) * GK + k0 + tx;
        Th[o] = hb;
        Tl[o] = __float2half_rn(v - __half2float(hb));
    }
}

// ---------------- Flash attention, fp16 HMMA (fp32 accum) ------------------
// 128 q-rows / 8 warps / 256 threads; KV tiles of 64; 3-stage pipeline,
// single barrier per tile; fp16 single-precision operands; 2 CTAs/SM.
#define FROWB 144
#define FQ_TILE (128 * FROWB)        // 18432
#define FK_TILE (64 * FROWB)         // 9216
#define FV_TILE (64 * FROWB)         // 9216
#define FSTAGE (FK_TILE + FV_TILE)   // 18432
#define FSMEM (FQ_TILE + 3 * FSTAGE) // 73728 -> 2 CTAs/SM

__global__ void __launch_bounds__(256, 2)
flash_mma_kernel(const __half* __restrict__ q16, const __half* __restrict__ k16,
                 const __half* __restrict__ vt16, __half* __restrict__ y16)
{
    extern __shared__ char smem_raw[];
    const uint32_t sQ  = smem_u32(smem_raw);
    const uint32_t sKV = sQ + FQ_TILE;

    const int tid = threadIdx.x, lane = tid & 31, warp = tid >> 5;
    const int t0 = (gridDim.x - 1 - blockIdx.x) * 128;   // heavy-first
    const int h = blockIdx.y, b = blockIdx.z;
    const size_t bh = (size_t)b * HH + h;
    const int nkv = t0 / 64 + 2;

    // Q prefetch: 128 rows x 8 chunks = 1024 / 256 = 4 per thread
    #pragma unroll
    for (int i = 0; i < 4; i++) {
        int idx = i * 256 + tid;
        int r = idx >> 3, j = idx & 7;
        cp_async16(sQ + r * FROWB + j * 16, q16 + (bh * TT + t0 + r) * 64 + j * 8);
    }
    auto pref_kv = [&](int n) {
        const uint32_t sb = sKV + (uint32_t)(n % 3) * FSTAGE;
        const int j0 = n * 64;
        #pragma unroll
        for (int i = 0; i < 4; i++) {
            int idx = i * 256 + tid;
            int arr = idx >> 9, r = (idx >> 3) & 63, j = idx & 7;
            const __half* g = arr ? (vt16 + (bh * 64 + r) * TT + j0 + j * 8)
                                  : (k16 + (bh * TT + j0 + r) * 64 + j * 8);
            cp_async16(sb + arr * FK_TILE + r * FROWB + j * 16, g);
        }
    };
    pref_kv(0);
    asm volatile("cp.async.commit_group;" ::: "memory");
    pref_kv(1);
    asm volatile("cp.async.commit_group;" ::: "memory");

    const int wrow = t0 + warp * 16;
    const int gr = lane >> 2;
    const int qk = (lane & 3) * 2;
    const int row0 = wrow + gr;
    const int row1 = row0 + 8;

    uint32_t qa[4][4];
    float O[8][4];
    #pragma unroll
    for (int nt = 0; nt < 8; nt++)
        #pragma unroll
        for (int e = 0; e < 4; e++) O[nt][e] = 0.f;
    float mA = -1e30f, mB = -1e30f, lA = 0.f, lB = 0.f;

    const uint32_t bBaseOff = ((lane & 7) + ((lane >> 4) << 3)) * FROWB + (((lane >> 3) & 1) << 4);

    for (int n = 0; n < nkv; n++) {
        asm volatile("cp.async.wait_group 1;" ::: "memory");
        __syncthreads();   // single barrier; 3-stage overwrite safety

        if (n == 0) {
            const uint32_t qb = sQ + (warp * 16 + (lane & 15)) * FROWB + ((lane >> 4) << 4);
            #pragma unroll
            for (int ks = 0; ks < 4; ks++)
                ldsm_x4(qa[ks][0], qa[ks][1], qa[ks][2], qa[ks][3], qb + ks * 32);
        }

        const int j0 = n * 64;
        if (j0 <= wrow + 15) {
            const uint32_t sb = sKV + (uint32_t)(n % 3) * FSTAGE;
            float S[8][4];
            #pragma unroll
            for (int nt = 0; nt < 8; nt++)
                #pragma unroll
                for (int e = 0; e < 4; e++) S[nt][e] = 0.f;

            // ---- S = Q K^T (fp16, 1 MMA per tile) ----
            #pragma unroll
            for (int ks = 0; ks < 4; ks++) {
                uint32_t B0[8], B1[8];
                #pragma unroll
                for (int q2 = 0; q2 < 4; q2++) {
                    const uint32_t off = bBaseOff + q2 * (16 * FROWB) + ks * 32;
                    ldsm_x4(B0[q2*2], B1[q2*2], B0[q2*2+1], B1[q2*2+1], sb + off);
                }
                #pragma unroll
                for (int nt = 0; nt < 8; nt++) {
                    float* c = S[nt];
                    mma16816(c[0], c[1], c[2], c[3],
                             qa[ks][0], qa[ks][1], qa[ks][2], qa[ks][3], B0[nt], B1[nt]);
                }
            }

            // ---- causal mask ----
            if (j0 + 63 > wrow) {
                #pragma unroll
                for (int nt = 0; nt < 8; nt++) {
                    const int c0 = j0 + nt * 8 + qk;
                    if (c0 > row0)     S[nt][0] = -1e30f;
                    if (c0 + 1 > row0) S[nt][1] = -1e30f;
                    if (c0 > row1)     S[nt][2] = -1e30f;
                    if (c0 + 1 > row1) S[nt][3] = -1e30f;
                }
            }

            // ---- online softmax ----
            float tmA = -1e30f, tmB = -1e30f;
            #pragma unroll
            for (int nt = 0; nt < 8; nt++) {
                tmA = fmaxf(tmA, fmaxf(S[nt][0], S[nt][1]));
                tmB = fmaxf(tmB, fmaxf(S[nt][2], S[nt][3]));
            }
            tmA = fmaxf(tmA, __shfl_xor_sync(0xffffffffu, tmA, 1));
            tmA = fmaxf(tmA, __shfl_xor_sync(0xffffffffu, tmA, 2));
            tmB = fmaxf(tmB, __shfl_xor_sync(0xffffffffu, tmB, 1));
            tmB = fmaxf(tmB, __shfl_xor_sync(0xffffffffu, tmB, 2));
            const float mnA = fmaxf(mA, tmA), mnB = fmaxf(mB, tmB);
            const float aA = __expf(mA - mnA), aB = __expf(mB - mnB);
            float sumA = 0.f, sumB = 0.f;
            #pragma unroll
            for (int nt = 0; nt < 8; nt++) {
                S[nt][0] = __expf(S[nt][0] - mnA);
                S[nt][1] = __expf(S[nt][1] - mnA);
                S[nt][2] = __expf(S[nt][2] - mnB);
                S[nt][3] = __expf(S[nt][3] - mnB);
                sumA += S[nt][0] + S[nt][1];
                sumB += S[nt][2] + S[nt][3];
            }
            sumA += __shfl_xor_sync(0xffffffffu, sumA, 1);
            sumA += __shfl_xor_sync(0xffffffffu, sumA, 2);
            sumB += __shfl_xor_sync(0xffffffffu, sumB, 1);
            sumB += __shfl_xor_sync(0xffffffffu, sumB, 2);
            lA = lA * aA + sumA;
            lB = lB * aB + sumB;
            mA = mnA; mB = mnB;
            #pragma unroll
            for (int nt = 0; nt < 8; nt++) {
                O[nt][0] *= aA; O[nt][1] *= aA;
                O[nt][2] *= aB; O[nt][3] *= aB;
            }

            // ---- O += P V (fp16, 1 MMA per tile) ----
            const uint32_t vb = sb + FK_TILE;
            #pragma unroll
            for (int ks = 0; ks < 4; ks++) {
                const int n0t = 2 * ks, n1t = 2 * ks + 1;
                uint32_t pa[4];
                pa[0] = pack_h16(S[n0t][0], S[n0t][1]);
                pa[1] = pack_h16(S[n0t][2], S[n0t][3]);
                pa[2] = pack_h16(S[n1t][0], S[n1t][1]);
                pa[3] = pack_h16(S[n1t][2], S[n1t][3]);
                uint32_t V0[8], V1[8];
                #pragma unroll
                for (int q2 = 0; q2 < 4; q2++) {
                    const uint32_t off = bBaseOff + q2 * (16 * FROWB) + ks * 32;
                    ldsm_x4(V0[q2*2], V1[q2*2], V0[q2*2+1], V1[q2*2+1], vb + off);
                }
                #pragma unroll
                for (int nt = 0; nt < 8; nt++) {
                    float* c = O[nt];
                    mma16816(c[0], c[1], c[2], c[3],
                             pa[0], pa[1], pa[2], pa[3], V0[nt], V1[nt]);
                }
            }
        }
        if (n + 2 < nkv) pref_kv(n + 2);
        asm volatile("cp.async.commit_group;" ::: "memory");
    }

    const float iA = 1.f / lA, iB = 1.f / lB;
    #pragma unroll
    for (int nt = 0; nt < 8; nt++) {
        const size_t d0 = (size_t)h * 64 + nt * 8 + qk;
        store_h2(y16, ((size_t)b * TT + row0) * CC + d0, O[nt][0] * iA, O[nt][1] * iA);
        store_h2(y16, ((size_t)b * TT + row1) * CC + d0, O[nt][2] * iB, O[nt][3] * iB);
    }
}

// ---------------- launch ---------------------------------------------------
extern "C" void kernel_launch(void* const* d_in, const int* in_sizes, int n_in,
                              void* d_out, int out_size)
{
    const float* x   = (const float*)d_in[0];
    const float* Wq  = (const float*)d_in[1];
    const float* Wkv = (const float*)d_in[2];
    const float* Wc  = (const float*)d_in[3];
    float* out = (float*)d_out;

    float *gc, *gs;
    __half *x16, *y16, *q16, *k16, *vt16, *wh, *wl, *wch, *wcl;
    cudaGetSymbolAddress((void**)&gc, g_cos);
    cudaGetSymbolAddress((void**)&gs, g_sin);
    cudaGetSymbolAddress((void**)&x16, g_x16);
    cudaGetSymbolAddress((void**)&y16, g_y16);
    cudaGetSymbolAddress((void**)&q16, g_q16);
    cudaGetSymbolAddress((void**)&k16, g_k16);
    cudaGetSymbolAddress((void**)&vt16, g_vt16);
    cudaGetSymbolAddress((void**)&wh, g_wh);
    cudaGetSymbolAddress((void**)&wl, g_wl);
    cudaGetSymbolAddress((void**)&wch, g_wch);
    cudaGetSymbolAddress((void**)&wcl, g_wcl);

    cudaFuncSetAttribute(gemm_kernel_mma, cudaFuncAttributeMaxDynamicSharedMemorySize, SMEM_DYN);
    cudaFuncSetAttribute(flash_mma_kernel, cudaFuncAttributeMaxDynamicSharedMemorySize, FSMEM);

    // #0: x -> fp16
    {
        int n4 = MM * GK / 4;
        split_kernel<<<(n4 + 255) / 256, 256>>>((const float4*)x, (uint2*)x16, n4);
    }
    // #1: weight transposes (fp16 hi/lo) + rope table
    transpose_split_all<<<dim3(128, GK / 32 + 1), dim3(32, 8)>>>(
        Wq, Wkv, Wc, wh, wl, wch, wcl, gc, gs);

    // #2: fused QKV GEMM
    gemm_kernel_mma<<<dim3(3 * CC / 128, MM / 128), 256, SMEM_DYN>>>(
        x16, wh, wl, nullptr, 3 * CC, 1, gc, gs, q16, k16, vt16);

    // #3: attention (ncu target)
    flash_mma_kernel<<<dim3(TT / 128, HH, BB), 256, FSMEM>>>(q16, k16, vt16, y16);

    // #4: out = y @ Wc
    gemm_kernel_mma<<<dim3(CC / 128, MM / 128), 256, SMEM_DYN>>>(
        y16, wch, wcl, out, CC, 0, nullptr, nullptr, nullptr, nullptr, nullptr);
}

// round 12
// speedup vs baseline: 1.6379x; 1.0265x over previous
#include <cuda_runtime.h>
#include <cuda_fp16.h>
#include <math.h>
#include <stdint.h>

#define BB 4
#define TT 2048
#define HH 16
#define DD 64
#define CC (HH*DD)      // 1024
#define MM (BB*TT)      // 8192
#define GK 1024         // K of all GEMMs

// ---------------- scratch (device globals; no allocation allowed) ----------
__device__ __align__(256) float g_cos[TT * 32];
__device__ __align__(256) float g_sin[TT * 32];

__device__ __align__(256) __half g_x16[(size_t)MM * GK];
__device__ __align__(256) __half g_y16[(size_t)MM * GK];
__device__ __align__(256) __half g_q16[(size_t)BB*HH*TT*DD];
__device__ __align__(256) __half g_k16[(size_t)BB*HH*TT*DD];
__device__ __align__(256) __half g_vt16[(size_t)BB*HH*TT*DD];
// weights transposed [N,K], fp16 hi + lo
__device__ __align__(256) __half g_wh[(size_t)3 * CC * GK];
__device__ __align__(256) __half g_wl[(size_t)3 * CC * GK];
__device__ __align__(256) __half g_wch[(size_t)CC * GK];
__device__ __align__(256) __half g_wcl[(size_t)CC * GK];

// ---------------- helpers ----------------------------------------------------
__device__ __forceinline__ uint32_t smem_u32(const void* p) {
    return (uint32_t)__cvta_generic_to_shared(p);
}

__device__ __forceinline__ void cp_async16(uint32_t saddr, const void* gaddr) {
    asm volatile("cp.async.cg.shared.global [%0], [%1], 16;" :: "r"(saddr), "l"(gaddr) : "memory");
}

__device__ __forceinline__ void ldsm_x4(uint32_t& r0, uint32_t& r1, uint32_t& r2, uint32_t& r3,
                                        uint32_t addr) {
    asm volatile("ldmatrix.sync.aligned.m8n8.x4.shared.b16 {%0,%1,%2,%3}, [%4];"
                 : "=r"(r0), "=r"(r1), "=r"(r2), "=r"(r3) : "r"(addr));
}

__device__ __forceinline__ void mma16816(float& c0, float& c1, float& c2, float& c3,
                                         uint32_t a0, uint32_t a1, uint32_t a2, uint32_t a3,
                                         uint32_t b0, uint32_t b1) {
    asm volatile(
        "mma.sync.aligned.m16n8k16.row.col.f32.f16.f16.f32 "
        "{%0,%1,%2,%3}, {%4,%5,%6,%7}, {%8,%9}, {%0,%1,%2,%3};"
        : "+f"(c0), "+f"(c1), "+f"(c2), "+f"(c3)
        : "r"(a0), "r"(a1), "r"(a2), "r"(a3), "r"(b0), "r"(b1));
}

__device__ __forceinline__ uint32_t pack_h16(float a, float b) {
    __half2 t = __floats2half2_rn(a, b);
    return *reinterpret_cast<uint32_t*>(&t);
}

__device__ __forceinline__ void store_h2(__half* dst, size_t off, float a, float b) {
    *reinterpret_cast<__half2*>(dst + off) = __floats2half2_rn(a, b);
}

// ---------------- HMMA GEMM: C = A16 @ (Bh+Bl)^T ---------------------------
// 128x128 CTA tile, 8 warps (2m x 4n), warp tile 64x32, 3-stage cp.async
// pipeline, ONE barrier per k-chunk, XOR-swizzled 64B rows, 2 CTAs/SM.
#define BK 32
#define NUMK (GK / BK)          // 32
#define ROWB 64                 // 64B data (32 fp16), swizzled
#define TILE_B (128 * ROWB)     // 8192
#define STAGE_B (3 * TILE_B)    // 24576 (A, Bh, Bl)
#define SMEM_DYN (3 * STAGE_B)  // 73728 -> 2 CTAs/SM

__global__ void __launch_bounds__(256, 2)
gemm_kernel_mma(const __half* __restrict__ A16,
                const __half* __restrict__ Bh, const __half* __restrict__ Bl,
                float* __restrict__ Cm, int Ndim, int mode,
                const float* __restrict__ gcos, const float* __restrict__ gsin,
                __half* __restrict__ q16, __half* __restrict__ k16,
                __half* __restrict__ vt16)
{
    extern __shared__ char smem_raw[];
    const uint32_t sbase = smem_u32(smem_raw);

    const int tid  = threadIdx.x;
    const int lane = tid & 31;
    const int warp = tid >> 5;
    const int mw   = warp & 1;
    const int nw   = warp >> 1;
    const int m0 = blockIdx.y * 128;
    const int n0 = blockIdx.x * 128;

    auto prefetch = [&](int kc) {
        const uint32_t sstage = sbase + (uint32_t)(kc % 3) * STAGE_B;
        #pragma unroll
        for (int i = 0; i < 6; i++) {
            const int c = i * 256 + tid;
            const int tile = c >> 9;            // 0=A 1=Bh 2=Bl
            const int r = (c >> 2) & 127;
            const int j = c & 3;
            const __half* g;
            if (tile == 0)      g = A16 + (size_t)(m0 + r) * GK + kc * BK + j * 8;
            else if (tile == 1) g = Bh  + (size_t)(n0 + r) * GK + kc * BK + j * 8;
            else                g = Bl  + (size_t)(n0 + r) * GK + kc * BK + j * 8;
            cp_async16(sstage + tile * TILE_B + r * ROWB + ((j ^ ((r >> 1) & 3)) << 4), g);
        }
    };

    prefetch(0);
    asm volatile("cp.async.commit_group;" ::: "memory");
    prefetch(1);
    asm volatile("cp.async.commit_group;" ::: "memory");

    const uint32_t aRowBase = (uint32_t)((mw * 64 + (lane & 15)) * ROWB);
    const uint32_t xa = ((lane & 15) >> 1) & 3;
    const uint32_t bRowBase = (uint32_t)((nw * 32 + (lane & 7) + ((lane >> 4) << 3)) * ROWB);
    const uint32_t xb = ((lane & 7) >> 1) & 3;
    const uint32_t aHalf = (lane >> 4);
    const uint32_t bHalf = ((lane >> 3) & 1);

    float acc[4][4][4];
    #pragma unroll
    for (int mt = 0; mt < 4; mt++)
        #pragma unroll
        for (int nt = 0; nt < 4; nt++)
            #pragma unroll
            for (int e = 0; e < 4; e++) acc[mt][nt][e] = 0.f;

    for (int kc = 0; kc < NUMK; kc++) {
        asm volatile("cp.async.wait_group 1;" ::: "memory");
        __syncthreads();

        const uint32_t sstage = sbase + (uint32_t)(kc % 3) * STAGE_B;
        const uint32_t aTile  = sstage;
        const uint32_t bTileH = sstage + TILE_B;
        const uint32_t bTileL = sstage + 2 * TILE_B;

        #pragma unroll
        for (int ks = 0; ks < 2; ks++) {
            const uint32_t aOff = ((uint32_t)(ks * 2 + aHalf) ^ xa) << 4;
            const uint32_t bOff = ((uint32_t)(ks * 2 + bHalf) ^ xb) << 4;
            uint32_t bh[4][2], bl[4][2];
            #pragma unroll
            for (int np = 0; np < 2; np++) {
                const uint32_t off = bRowBase + np * (16 * ROWB) + bOff;
                ldsm_x4(bh[np*2][0], bh[np*2][1], bh[np*2+1][0], bh[np*2+1][1], bTileH + off);
                ldsm_x4(bl[np*2][0], bl[np*2][1], bl[np*2+1][0], bl[np*2+1][1], bTileL + off);
            }
            #pragma unroll
            for (int mt = 0; mt < 4; mt++) {
                uint32_t ah[4];
                const uint32_t off = aRowBase + mt * (16 * ROWB) + aOff;
                ldsm_x4(ah[0], ah[1], ah[2], ah[3], aTile + off);
                #pragma unroll
                for (int nt = 0; nt < 4; nt++) {
                    float* c = acc[mt][nt];
                    mma16816(c[0], c[1], c[2], c[3],
                             ah[0], ah[1], ah[2], ah[3], bh[nt][0], bh[nt][1]);
                    mma16816(c[0], c[1], c[2], c[3],
                             ah[0], ah[1], ah[2], ah[3], bl[nt][0], bl[nt][1]);
                }
            }
        }
        if (kc + 2 < NUMK) prefetch(kc + 2);
        asm volatile("cp.async.commit_group;" ::: "memory");
    }

    if (mode == 0) {
        const int rbase = m0 + mw * 64 + (lane >> 2);
        const int cbase = n0 + nw * 32 + ((lane & 3) << 1);
        #pragma unroll
        for (int mt = 0; mt < 4; mt++) {
            #pragma unroll
            for (int nt = 0; nt < 4; nt++) {
                float* c = acc[mt][nt];
                float* p0 = Cm + (size_t)(rbase + mt * 16) * Ndim + cbase + nt * 8;
                float* p1 = p0 + (size_t)8 * Ndim;
                *reinterpret_cast<float2*>(p0) = make_float2(c[0], c[1]);
                *reinterpret_cast<float2*>(p1) = make_float2(c[2], c[3]);
            }
        }
        return;
    }

    // ---- fused QKV epilogue: stage fp32 tile in smem [128][132] ----
    float* sm = reinterpret_cast<float*>(smem_raw);
    __syncthreads();
    const int rloc = mw * 64 + (lane >> 2);
    const int cloc = nw * 32 + ((lane & 3) << 1);
    #pragma unroll
    for (int mt = 0; mt < 4; mt++) {
        #pragma unroll
        for (int nt = 0; nt < 4; nt++) {
            float* c = acc[mt][nt];
            float* p0 = sm + (size_t)(rloc + mt * 16) * 132 + cloc + nt * 8;
            *reinterpret_cast<float2*>(p0)           = make_float2(c[0], c[1]);
            *reinterpret_cast<float2*>(p0 + 8 * 132) = make_float2(c[2], c[3]);
        }
    }
    __syncthreads();

    const int ct = blockIdx.x;
    const int b = m0 >> 11;
    const int t_base = m0 & (TT - 1);

    if (ct < 16) {
        const bool isQ = (ct < 8);
        // Q scale folds 1/sqrt(D) AND log2(e): flash softmax runs in exp2 domain
        const float qs = isQ ? (0.125f * 1.4426950408889634f) : 1.0f;
        __half* dst = isQ ? q16 : k16;
        const int hbase = (isQ ? ct : (ct - 8)) * 2;
        #pragma unroll
        for (int i = 0; i < 16; i++) {
            const int idx = i * 256 + tid;
            const int dp = (idx & 15) * 2;
            const int hs = (idx >> 4) & 1;
            const int r  = idx >> 5;
            const int t  = t_base + r;
            const float c0 = gcos[t * 32 + dp],  c1 = gcos[t * 32 + dp + 1];
            const float s0 = gsin[t * 32 + dp],  s1 = gsin[t * 32 + dp + 1];
            const float* row = sm + (size_t)r * 132 + hs * 64;
            const float x1 = row[dp],      x1b = row[dp + 1];
            const float x2 = row[dp + 32], x2b = row[dp + 33];
            const float o0 = (x1 * c0 - x2 * s0) * qs;
            const float o1 = (x1b * c1 - x2b * s1) * qs;
            const float o2 = (x2 * c0 + x1 * s0) * qs;
            const float o3 = (x2b * c1 + x1b * s1) * qs;
            const size_t base = (((size_t)b * HH + hbase + hs) * TT + t) * 64;
            store_h2(dst, base + dp, o0, o1);
            store_h2(dst, base + dp + 32, o2, o3);
        }
    } else {
        const int hbase = (ct - 16) * 2;
        #pragma unroll
        for (int i = 0; i < 32; i++) {
            const int idx = i * 256 + tid;
            const int c  = idx >> 6;
            const int t2 = idx & 63;
            const int hs = c >> 6;
            const int d  = c & 63;
            const float a  = sm[(size_t)(2 * t2) * 132 + c];
            const float bv = sm[(size_t)(2 * t2 + 1) * 132 + c];
            const int t = t_base + 2 * t2;
            store_h2(vt16, (((size_t)b * HH + hbase + hs) * 64 + d) * TT + t, a, bv);
        }
    }
}

// ---------------- fp32 -> fp16 convert -------------------------------------
__global__ void split_kernel(const float4* __restrict__ in, uint2* __restrict__ out, int n4)
{
    int i = blockIdx.x * blockDim.x + threadIdx.x;
    if (i >= n4) return;
    float4 v = in[i];
    __half2 a = __floats2half2_rn(v.x, v.y);
    __half2 b = __floats2half2_rn(v.z, v.w);
    uint2 o;
    o.x = *reinterpret_cast<uint32_t*>(&a);
    o.y = *reinterpret_cast<uint32_t*>(&b);
    out[i] = o;
}

// -------- combined W transpose-split (fp16 hi/lo) + RoPE table -------------
__global__ void transpose_split_all(const float* __restrict__ Wq,
                                    const float* __restrict__ Wkv,
                                    const float* __restrict__ Wc,
                                    __half* __restrict__ wh, __half* __restrict__ wl,
                                    __half* __restrict__ wch, __half* __restrict__ wcl,
                                    float* __restrict__ gcos, float* __restrict__ gsin)
{
    const int tx = threadIdx.x, ty = threadIdx.y;
    if (blockIdx.y == 32) {
        const int tid = ty * 32 + tx;
        #pragma unroll
        for (int e = 0; e < 2; e++) {
            int i = blockIdx.x * 512 + e * 256 + tid;
            int t = i >> 5;
            int d = i & 31;
            float inv = (float)exp(-((double)(2 * d) / 64.0) * log(10000.0));
            float ang = (float)t * inv;
            gcos[i] = cosf(ang);
            gsin[i] = sinf(ang);
        }
        return;
    }

    __shared__ float t[32][33];
    const int nx = blockIdx.x;
    const int k0 = blockIdx.y * 32;
    const float* W;
    __half *Th, *Tl;
    int N, n0;
    if (nx < 32)       { W = Wq;  N = CC;     n0 = nx * 32;        Th = wh;  Tl = wl; }
    else if (nx < 96)  { W = Wkv; N = 2 * CC; n0 = (nx - 32) * 32;
                         Th = wh + (size_t)CC * GK; Tl = wl + (size_t)CC * GK; }
    else               { W = Wc;  N = CC;     n0 = (nx - 96) * 32; Th = wch; Tl = wcl; }

    #pragma unroll
    for (int i = 0; i < 32; i += 8)
        t[ty + i][tx] = W[(size_t)(k0 + ty + i) * N + n0 + tx];
    __syncthreads();
    #pragma unroll
    for (int i = 0; i < 32; i += 8) {
        float v = t[tx][ty + i];
        __half hb = __float2half_rn(v);
        size_t o = (size_t)(n0 + ty + i) * GK + k0 + tx;
        Th[o] = hb;
        Tl[o] = __float2half_rn(v - __half2float(hb));
    }
}

// ---------------- Flash attention, fp16 HMMA, exp2-domain softmax ----------
// 128 q-rows / 8 warps / 256 threads; KV tiles of 64; 3-stage pipeline,
// single barrier per tile; 2 CTAs/SM. Scores arrive pre-scaled by log2(e)/8.
#define FROWB 144
#define FQ_TILE (128 * FROWB)        // 18432
#define FK_TILE (64 * FROWB)         // 9216
#define FV_TILE (64 * FROWB)         // 9216
#define FSTAGE (FK_TILE + FV_TILE)   // 18432
#define FSMEM (FQ_TILE + 3 * FSTAGE) // 73728 -> 2 CTAs/SM

__global__ void __launch_bounds__(256, 2)
flash_mma_kernel(const __half* __restrict__ q16, const __half* __restrict__ k16,
                 const __half* __restrict__ vt16, __half* __restrict__ y16)
{
    extern __shared__ char smem_raw[];
    const uint32_t sQ  = smem_u32(smem_raw);
    const uint32_t sKV = sQ + FQ_TILE;

    const int tid = threadIdx.x, lane = tid & 31, warp = tid >> 5;
    const int t0 = (gridDim.x - 1 - blockIdx.x) * 128;   // heavy-first
    const int h = blockIdx.y, b = blockIdx.z;
    const size_t bh = (size_t)b * HH + h;
    const int nkv = t0 / 64 + 2;

    #pragma unroll
    for (int i = 0; i < 4; i++) {
        int idx = i * 256 + tid;
        int r = idx >> 3, j = idx & 7;
        cp_async16(sQ + r * FROWB + j * 16, q16 + (bh * TT + t0 + r) * 64 + j * 8);
    }
    auto pref_kv = [&](int n) {
        const uint32_t sb = sKV + (uint32_t)(n % 3) * FSTAGE;
        const int j0 = n * 64;
        #pragma unroll
        for (int i = 0; i < 4; i++) {
            int idx = i * 256 + tid;
            int arr = idx >> 9, r = (idx >> 3) & 63, j = idx & 7;
            const __half* g = arr ? (vt16 + (bh * 64 + r) * TT + j0 + j * 8)
                                  : (k16 + (bh * TT + j0 + r) * 64 + j * 8);
            cp_async16(sb + arr * FK_TILE + r * FROWB + j * 16, g);
        }
    };
    pref_kv(0);
    asm volatile("cp.async.commit_group;" ::: "memory");
    pref_kv(1);
    asm volatile("cp.async.commit_group;" ::: "memory");

    const int wrow = t0 + warp * 16;
    const int gr = lane >> 2;
    const int qk = (lane & 3) * 2;
    const int row0 = wrow + gr;
    const int row1 = row0 + 8;

    uint32_t qa[4][4];
    float O[8][4];
    #pragma unroll
    for (int nt = 0; nt < 8; nt++)
        #pragma unroll
        for (int e = 0; e < 4; e++) O[nt][e] = 0.f;
    float mA = -1e30f, mB = -1e30f, lA = 0.f, lB = 0.f;   // l = per-thread partial

    const uint32_t bBaseOff = ((lane & 7) + ((lane >> 4) << 3)) * FROWB + (((lane >> 3) & 1) << 4);

    for (int n = 0; n < nkv; n++) {
        asm volatile("cp.async.wait_group 1;" ::: "memory");
        __syncthreads();

        if (n == 0) {
            const uint32_t qb = sQ + (warp * 16 + (lane & 15)) * FROWB + ((lane >> 4) << 4);
            #pragma unroll
            for (int ks = 0; ks < 4; ks++)
                ldsm_x4(qa[ks][0], qa[ks][1], qa[ks][2], qa[ks][3], qb + ks * 32);
        }

        const int j0 = n * 64;
        if (j0 <= wrow + 15) {
            const uint32_t sb = sKV + (uint32_t)(n % 3) * FSTAGE;
            float S[8][4];
            #pragma unroll
            for (int nt = 0; nt < 8; nt++)
                #pragma unroll
                for (int e = 0; e < 4; e++) S[nt][e] = 0.f;

            // ---- S = Q K^T ----
            #pragma unroll
            for (int ks = 0; ks < 4; ks++) {
                uint32_t B0[8], B1[8];
                #pragma unroll
                for (int q2 = 0; q2 < 4; q2++) {
                    const uint32_t off = bBaseOff + q2 * (16 * FROWB) + ks * 32;
                    ldsm_x4(B0[q2*2], B1[q2*2], B0[q2*2+1], B1[q2*2+1], sb + off);
                }
                #pragma unroll
                for (int nt = 0; nt < 8; nt++) {
                    float* c = S[nt];
                    mma16816(c[0], c[1], c[2], c[3],
                             qa[ks][0], qa[ks][1], qa[ks][2], qa[ks][3], B0[nt], B1[nt]);
                }
            }

            // ---- causal mask ----
            if (j0 + 63 > wrow) {
                #pragma unroll
                for (int nt = 0; nt < 8; nt++) {
                    const int c0 = j0 + nt * 8 + qk;
                    if (c0 > row0)     S[nt][0] = -1e30f;
                    if (c0 + 1 > row0) S[nt][1] = -1e30f;
                    if (c0 > row1)     S[nt][2] = -1e30f;
                    if (c0 + 1 > row1) S[nt][3] = -1e30f;
                }
            }

            // ---- online softmax (exp2 domain) ----
            float tmA = -1e30f, tmB = -1e30f;
            #pragma unroll
            for (int nt = 0; nt < 8; nt++) {
                tmA = fmaxf(tmA, fmaxf(S[nt][0], S[nt][1]));
                tmB = fmaxf(tmB, fmaxf(S[nt][2], S[nt][3]));
            }
            tmA = fmaxf(tmA, __shfl_xor_sync(0xffffffffu, tmA, 1));
            tmA = fmaxf(tmA, __shfl_xor_sync(0xffffffffu, tmA, 2));
            tmB = fmaxf(tmB, __shfl_xor_sync(0xffffffffu, tmB, 1));
            tmB = fmaxf(tmB, __shfl_xor_sync(0xffffffffu, tmB, 2));

            // rescale only when the running max actually increases (exact skip)
            if (__any_sync(0xffffffffu, (tmA > mA) || (tmB > mB))) {
                const float mnA = fmaxf(mA, tmA), mnB = fmaxf(mB, tmB);
                const float aA = exp2f(mA - mnA), aB = exp2f(mB - mnB);
                lA *= aA; lB *= aB;
                #pragma unroll
                for (int nt = 0; nt < 8; nt++) {
                    O[nt][0] *= aA; O[nt][1] *= aA;
                    O[nt][2] *= aB; O[nt][3] *= aB;
                }
                mA = mnA; mB = mnB;
            }

            float sumA = 0.f, sumB = 0.f;
            #pragma unroll
            for (int nt = 0; nt < 8; nt++) {
                S[nt][0] = exp2f(S[nt][0] - mA);
                S[nt][1] = exp2f(S[nt][1] - mA);
                S[nt][2] = exp2f(S[nt][2] - mB);
                S[nt][3] = exp2f(S[nt][3] - mB);
                sumA += S[nt][0] + S[nt][1];
                sumB += S[nt][2] + S[nt][3];
            }
            lA += sumA;    // per-thread partial; quad-reduced in epilogue
            lB += sumB;

            // ---- O += P V ----
            const uint32_t vb = sb + FK_TILE;
            #pragma unroll
            for (int ks = 0; ks < 4; ks++) {
                const int n0t = 2 * ks, n1t = 2 * ks + 1;
                uint32_t pa[4];
                pa[0] = pack_h16(S[n0t][0], S[n0t][1]);
                pa[1] = pack_h16(S[n0t][2], S[n0t][3]);
                pa[2] = pack_h16(S[n1t][0], S[n1t][1]);
                pa[3] = pack_h16(S[n1t][2], S[n1t][3]);
                uint32_t V0[8], V1[8];
                #pragma unroll
                for (int q2 = 0; q2 < 4; q2++) {
                    const uint32_t off = bBaseOff + q2 * (16 * FROWB) + ks * 32;
                    ldsm_x4(V0[q2*2], V1[q2*2], V0[q2*2+1], V1[q2*2+1], vb + off);
                }
                #pragma unroll
                for (int nt = 0; nt < 8; nt++) {
                    float* c = O[nt];
                    mma16816(c[0], c[1], c[2], c[3],
                             pa[0], pa[1], pa[2], pa[3], V0[nt], V1[nt]);
                }
            }
        }
        if (n + 2 < nkv) pref_kv(n + 2);
        asm volatile("cp.async.commit_group;" ::: "memory");
    }

    // quad-reduce the deferred l partials (lanes differ only in qk = lane&3)
    lA += __shfl_xor_sync(0xffffffffu, lA, 1);
    lA += __shfl_xor_sync(0xffffffffu, lA, 2);
    lB += __shfl_xor_sync(0xffffffffu, lB, 1);
    lB += __shfl_xor_sync(0xffffffffu, lB, 2);

    const float iA = 1.f / lA, iB = 1.f / lB;
    #pragma unroll
    for (int nt = 0; nt < 8; nt++) {
        const size_t d0 = (size_t)h * 64 + nt * 8 + qk;
        store_h2(y16, ((size_t)b * TT + row0) * CC + d0, O[nt][0] * iA, O[nt][1] * iA);
        store_h2(y16, ((size_t)b * TT + row1) * CC + d0, O[nt][2] * iB, O[nt][3] * iB);
    }
}

// ---------------- launch ---------------------------------------------------
extern "C" void kernel_launch(void* const* d_in, const int* in_sizes, int n_in,
                              void* d_out, int out_size)
{
    const float* x   = (const float*)d_in[0];
    const float* Wq  = (const float*)d_in[1];
    const float* Wkv = (const float*)d_in[2];
    const float* Wc  = (const float*)d_in[3];
    float* out = (float*)d_out;

    float *gc, *gs;
    __half *x16, *y16, *q16, *k16, *vt16, *wh, *wl, *wch, *wcl;
    cudaGetSymbolAddress((void**)&gc, g_cos);
    cudaGetSymbolAddress((void**)&gs, g_sin);
    cudaGetSymbolAddress((void**)&x16, g_x16);
    cudaGetSymbolAddress((void**)&y16, g_y16);
    cudaGetSymbolAddress((void**)&q16, g_q16);
    cudaGetSymbolAddress((void**)&k16, g_k16);
    cudaGetSymbolAddress((void**)&vt16, g_vt16);
    cudaGetSymbolAddress((void**)&wh, g_wh);
    cudaGetSymbolAddress((void**)&wl, g_wl);
    cudaGetSymbolAddress((void**)&wch, g_wch);
    cudaGetSymbolAddress((void**)&wcl, g_wcl);

    cudaFuncSetAttribute(gemm_kernel_mma, cudaFuncAttributeMaxDynamicSharedMemorySize, SMEM_DYN);
    cudaFuncSetAttribute(flash_mma_kernel, cudaFuncAttributeMaxDynamicSharedMemorySize, FSMEM);

    // #0: x -> fp16
    {
        int n4 = MM * GK / 4;
        split_kernel<<<(n4 + 255) / 256, 256>>>((const float4*)x, (uint2*)x16, n4);
    }
    // #1: weight transposes (fp16 hi/lo) + rope table
    transpose_split_all<<<dim3(128, GK / 32 + 1), dim3(32, 8)>>>(
        Wq, Wkv, Wc, wh, wl, wch, wcl, gc, gs);

    // #2: fused QKV GEMM
    gemm_kernel_mma<<<dim3(3 * CC / 128, MM / 128), 256, SMEM_DYN>>>(
        x16, wh, wl, nullptr, 3 * CC, 1, gc, gs, q16, k16, vt16);

    // #3: attention (ncu target)
    flash_mma_kernel<<<dim3(TT / 128, HH, BB), 256, FSMEM>>>(q16, k16, vt16, y16);

    // #4: out = y @ Wc
    gemm_kernel_mma<<<dim3(CC / 128, MM / 128), 256, SMEM_DYN>>>(
        y16, wch, wcl, out, CC, 0, nullptr, nullptr, nullptr, nullptr, nullptr);
}

// round 13
// speedup vs baseline: 2.2291x; 1.3609x over previous
#include <cuda_runtime.h>
#include <cuda_fp16.h>
#include <math.h>
#include <stdint.h>

#define BB 4
#define TT 2048
#define HH 16
#define DD 64
#define CC (HH*DD)      // 1024
#define MM (BB*TT)      // 8192
#define GK 1024         // K of all GEMMs

// ---------------- scratch (device globals; no allocation allowed) ----------
__device__ __align__(256) float g_cos[TT * 32];
__device__ __align__(256) float g_sin[TT * 32];

__device__ __align__(256) __half g_x16[(size_t)MM * GK];
__device__ __align__(256) __half g_y16[(size_t)MM * GK];
__device__ __align__(256) __half g_q16[(size_t)BB*HH*TT*DD];
__device__ __align__(256) __half g_k16[(size_t)BB*HH*TT*DD];
__device__ __align__(256) __half g_vt16[(size_t)BB*HH*TT*DD];
// weights transposed [N,K], single fp16
__device__ __align__(256) __half g_wh[(size_t)3 * CC * GK];
__device__ __align__(256) __half g_wch[(size_t)CC * GK];

// ---------------- helpers ----------------------------------------------------
__device__ __forceinline__ uint32_t smem_u32(const void* p) {
    return (uint32_t)__cvta_generic_to_shared(p);
}

__device__ __forceinline__ void cp_async16(uint32_t saddr, const void* gaddr) {
    asm volatile("cp.async.cg.shared.global [%0], [%1], 16;" :: "r"(saddr), "l"(gaddr) : "memory");
}

__device__ __forceinline__ void ldsm_x4(uint32_t& r0, uint32_t& r1, uint32_t& r2, uint32_t& r3,
                                        uint32_t addr) {
    asm volatile("ldmatrix.sync.aligned.m8n8.x4.shared.b16 {%0,%1,%2,%3}, [%4];"
                 : "=r"(r0), "=r"(r1), "=r"(r2), "=r"(r3) : "r"(addr));
}

__device__ __forceinline__ void mma16816(float& c0, float& c1, float& c2, float& c3,
                                         uint32_t a0, uint32_t a1, uint32_t a2, uint32_t a3,
                                         uint32_t b0, uint32_t b1) {
    asm volatile(
        "mma.sync.aligned.m16n8k16.row.col.f32.f16.f16.f32 "
        "{%0,%1,%2,%3}, {%4,%5,%6,%7}, {%8,%9}, {%0,%1,%2,%3};"
        : "+f"(c0), "+f"(c1), "+f"(c2), "+f"(c3)
        : "r"(a0), "r"(a1), "r"(a2), "r"(a3), "r"(b0), "r"(b1));
}

__device__ __forceinline__ uint32_t pack_h16(float a, float b) {
    __half2 t = __floats2half2_rn(a, b);
    return *reinterpret_cast<uint32_t*>(&t);
}

__device__ __forceinline__ void store_h2(__half* dst, size_t off, float a, float b) {
    *reinterpret_cast<__half2*>(dst + off) = __floats2half2_rn(a, b);
}

// ---------------- HMMA GEMM: C = A16 @ B16^T (single fp16) -----------------
// 128x128 CTA tile, 8 warps (2m x 4n), warp tile 64x32, 3-stage cp.async
// pipeline, ONE barrier per k-chunk, XOR-swizzled 64B rows, 2 CTAs/SM.
#define BK 32
#define NUMK (GK / BK)          // 32
#define ROWB 64                 // 64B data (32 fp16), swizzled
#define TILE_B (128 * ROWB)     // 8192
#define STAGE_B (2 * TILE_B)    // 16384 (A, B)
// dynamic smem: max(3 stages = 49152, fp32 epilogue staging 128*132*4 = 67584)
#define SMEM_DYN 67584

__global__ void __launch_bounds__(256, 2)
gemm_kernel_mma(const __half* __restrict__ A16, const __half* __restrict__ B16,
                float* __restrict__ Cm, int Ndim, int mode,
                const float* __restrict__ gcos, const float* __restrict__ gsin,
                __half* __restrict__ q16, __half* __restrict__ k16,
                __half* __restrict__ vt16)
{
    extern __shared__ char smem_raw[];
    const uint32_t sbase = smem_u32(smem_raw);

    const int tid  = threadIdx.x;
    const int lane = tid & 31;
    const int warp = tid >> 5;
    const int mw   = warp & 1;
    const int nw   = warp >> 1;
    const int m0 = blockIdx.y * 128;
    const int n0 = blockIdx.x * 128;

    auto prefetch = [&](int kc) {
        const uint32_t sstage = sbase + (uint32_t)(kc % 3) * STAGE_B;
        #pragma unroll
        for (int i = 0; i < 4; i++) {
            const int c = i * 256 + tid;        // 0..1023
            const int tile = c >> 9;            // 0=A 1=B
            const int r = (c >> 2) & 127;
            const int j = c & 3;
            const __half* g = (tile == 0)
                ? A16 + (size_t)(m0 + r) * GK + kc * BK + j * 8
                : B16 + (size_t)(n0 + r) * GK + kc * BK + j * 8;
            cp_async16(sstage + tile * TILE_B + r * ROWB + ((j ^ ((r >> 1) & 3)) << 4), g);
        }
    };

    prefetch(0);
    asm volatile("cp.async.commit_group;" ::: "memory");
    prefetch(1);
    asm volatile("cp.async.commit_group;" ::: "memory");

    const uint32_t aRowBase = (uint32_t)((mw * 64 + (lane & 15)) * ROWB);
    const uint32_t xa = ((lane & 15) >> 1) & 3;
    const uint32_t bRowBase = (uint32_t)((nw * 32 + (lane & 7) + ((lane >> 4) << 3)) * ROWB);
    const uint32_t xb = ((lane & 7) >> 1) & 3;
    const uint32_t aHalf = (lane >> 4);
    const uint32_t bHalf = ((lane >> 3) & 1);

    float acc[4][4][4];
    #pragma unroll
    for (int mt = 0; mt < 4; mt++)
        #pragma unroll
        for (int nt = 0; nt < 4; nt++)
            #pragma unroll
            for (int e = 0; e < 4; e++) acc[mt][nt][e] = 0.f;

    for (int kc = 0; kc < NUMK; kc++) {
        asm volatile("cp.async.wait_group 1;" ::: "memory");
        __syncthreads();

        const uint32_t sstage = sbase + (uint32_t)(kc % 3) * STAGE_B;
        const uint32_t aTile = sstage;
        const uint32_t bTile = sstage + TILE_B;

        #pragma unroll
        for (int ks = 0; ks < 2; ks++) {
            const uint32_t aOff = ((uint32_t)(ks * 2 + aHalf) ^ xa) << 4;
            const uint32_t bOff = ((uint32_t)(ks * 2 + bHalf) ^ xb) << 4;
            uint32_t bh[4][2];
            #pragma unroll
            for (int np = 0; np < 2; np++) {
                const uint32_t off = bRowBase + np * (16 * ROWB) + bOff;
                ldsm_x4(bh[np*2][0], bh[np*2][1], bh[np*2+1][0], bh[np*2+1][1], bTile + off);
            }
            #pragma unroll
            for (int mt = 0; mt < 4; mt++) {
                uint32_t ah[4];
                const uint32_t off = aRowBase + mt * (16 * ROWB) + aOff;
                ldsm_x4(ah[0], ah[1], ah[2], ah[3], aTile + off);
                #pragma unroll
                for (int nt = 0; nt < 4; nt++) {
                    float* c = acc[mt][nt];
                    mma16816(c[0], c[1], c[2], c[3],
                             ah[0], ah[1], ah[2], ah[3], bh[nt][0], bh[nt][1]);
                }
            }
        }
        if (kc + 2 < NUMK) prefetch(kc + 2);
        asm volatile("cp.async.commit_group;" ::: "memory");
    }

    if (mode == 0) {
        const int rbase = m0 + mw * 64 + (lane >> 2);
        const int cbase = n0 + nw * 32 + ((lane & 3) << 1);
        #pragma unroll
        for (int mt = 0; mt < 4; mt++) {
            #pragma unroll
            for (int nt = 0; nt < 4; nt++) {
                float* c = acc[mt][nt];
                float* p0 = Cm + (size_t)(rbase + mt * 16) * Ndim + cbase + nt * 8;
                float* p1 = p0 + (size_t)8 * Ndim;
                *reinterpret_cast<float2*>(p0) = make_float2(c[0], c[1]);
                *reinterpret_cast<float2*>(p1) = make_float2(c[2], c[3]);
            }
        }
        return;
    }

    // ---- fused QKV epilogue: stage fp32 tile in smem [128][132] ----
    float* sm = reinterpret_cast<float*>(smem_raw);
    __syncthreads();
    const int rloc = mw * 64 + (lane >> 2);
    const int cloc = nw * 32 + ((lane & 3) << 1);
    #pragma unroll
    for (int mt = 0; mt < 4; mt++) {
        #pragma unroll
        for (int nt = 0; nt < 4; nt++) {
            float* c = acc[mt][nt];
            float* p0 = sm + (size_t)(rloc + mt * 16) * 132 + cloc + nt * 8;
            *reinterpret_cast<float2*>(p0)           = make_float2(c[0], c[1]);
            *reinterpret_cast<float2*>(p0 + 8 * 132) = make_float2(c[2], c[3]);
        }
    }
    __syncthreads();

    const int ct = blockIdx.x;
    const int b = m0 >> 11;
    const int t_base = m0 & (TT - 1);

    if (ct < 16) {
        const bool isQ = (ct < 8);
        // Q scale folds 1/sqrt(D) AND log2(e): flash softmax runs in exp2 domain
        const float qs = isQ ? (0.125f * 1.4426950408889634f) : 1.0f;
        __half* dst = isQ ? q16 : k16;
        const int hbase = (isQ ? ct : (ct - 8)) * 2;
        #pragma unroll
        for (int i = 0; i < 16; i++) {
            const int idx = i * 256 + tid;
            const int dp = (idx & 15) * 2;
            const int hs = (idx >> 4) & 1;
            const int r  = idx >> 5;
            const int t  = t_base + r;
            const float c0 = gcos[t * 32 + dp],  c1 = gcos[t * 32 + dp + 1];
            const float s0 = gsin[t * 32 + dp],  s1 = gsin[t * 32 + dp + 1];
            const float* row = sm + (size_t)r * 132 + hs * 64;
            const float x1 = row[dp],      x1b = row[dp + 1];
            const float x2 = row[dp + 32], x2b = row[dp + 33];
            const float o0 = (x1 * c0 - x2 * s0) * qs;
            const float o1 = (x1b * c1 - x2b * s1) * qs;
            const float o2 = (x2 * c0 + x1 * s0) * qs;
            const float o3 = (x2b * c1 + x1b * s1) * qs;
            const size_t base = (((size_t)b * HH + hbase + hs) * TT + t) * 64;
            store_h2(dst, base + dp, o0, o1);
            store_h2(dst, base + dp + 32, o2, o3);
        }
    } else {
        const int hbase = (ct - 16) * 2;
        #pragma unroll
        for (int i = 0; i < 32; i++) {
            const int idx = i * 256 + tid;
            const int c  = idx >> 6;
            const int t2 = idx & 63;
            const int hs = c >> 6;
            const int d  = c & 63;
            const float a  = sm[(size_t)(2 * t2) * 132 + c];
            const float bv = sm[(size_t)(2 * t2 + 1) * 132 + c];
            const int t = t_base + 2 * t2;
            store_h2(vt16, (((size_t)b * HH + hbase + hs) * 64 + d) * TT + t, a, bv);
        }
    }
}

// ---------------- fp32 -> fp16 convert -------------------------------------
__global__ void split_kernel(const float4* __restrict__ in, uint2* __restrict__ out, int n4)
{
    int i = blockIdx.x * blockDim.x + threadIdx.x;
    if (i >= n4) return;
    float4 v = in[i];
    __half2 a = __floats2half2_rn(v.x, v.y);
    __half2 b = __floats2half2_rn(v.z, v.w);
    uint2 o;
    o.x = *reinterpret_cast<uint32_t*>(&a);
    o.y = *reinterpret_cast<uint32_t*>(&b);
    out[i] = o;
}

// -------- combined W transpose (single fp16) + RoPE table ------------------
__global__ void transpose_split_all(const float* __restrict__ Wq,
                                    const float* __restrict__ Wkv,
                                    const float* __restrict__ Wc,
                                    __half* __restrict__ wh, __half* __restrict__ wch,
                                    float* __restrict__ gcos, float* __restrict__ gsin)
{
    const int tx = threadIdx.x, ty = threadIdx.y;
    if (blockIdx.y == 32) {
        const int tid = ty * 32 + tx;
        #pragma unroll
        for (int e = 0; e < 2; e++) {
            int i = blockIdx.x * 512 + e * 256 + tid;
            int t = i >> 5;
            int d = i & 31;
            float inv = (float)exp(-((double)(2 * d) / 64.0) * log(10000.0));
            float ang = (float)t * inv;
            gcos[i] = cosf(ang);
            gsin[i] = sinf(ang);
        }
        return;
    }

    __shared__ float t[32][33];
    const int nx = blockIdx.x;
    const int k0 = blockIdx.y * 32;
    const float* W;
    __half* Th;
    int N, n0;
    if (nx < 32)       { W = Wq;  N = CC;     n0 = nx * 32;        Th = wh; }
    else if (nx < 96)  { W = Wkv; N = 2 * CC; n0 = (nx - 32) * 32;
                         Th = wh + (size_t)CC * GK; }
    else               { W = Wc;  N = CC;     n0 = (nx - 96) * 32; Th = wch; }

    #pragma unroll
    for (int i = 0; i < 32; i += 8)
        t[ty + i][tx] = W[(size_t)(k0 + ty + i) * N + n0 + tx];
    __syncthreads();
    #pragma unroll
    for (int i = 0; i < 32; i += 8) {
        float v = t[tx][ty + i];
        Th[(size_t)(n0 + ty + i) * GK + k0 + tx] = __float2half_rn(v);
    }
}

// ---------------- Flash attention, fp16 HMMA, exp2-domain softmax ----------
#define FROWB 144
#define FQ_TILE (128 * FROWB)        // 18432
#define FK_TILE (64 * FROWB)         // 9216
#define FV_TILE (64 * FROWB)         // 9216
#define FSTAGE (FK_TILE + FV_TILE)   // 18432
#define FSMEM (FQ_TILE + 3 * FSTAGE) // 73728 -> 2 CTAs/SM

__global__ void __launch_bounds__(256, 2)
flash_mma_kernel(const __half* __restrict__ q16, const __half* __restrict__ k16,
                 const __half* __restrict__ vt16, __half* __restrict__ y16)
{
    extern __shared__ char smem_raw[];
    const uint32_t sQ  = smem_u32(smem_raw);
    const uint32_t sKV = sQ + FQ_TILE;

    const int tid = threadIdx.x, lane = tid & 31, warp = tid >> 5;
    const int t0 = (gridDim.x - 1 - blockIdx.x) * 128;   // heavy-first
    const int h = blockIdx.y, b = blockIdx.z;
    const size_t bh = (size_t)b * HH + h;
    const int nkv = t0 / 64 + 2;

    #pragma unroll
    for (int i = 0; i < 4; i++) {
        int idx = i * 256 + tid;
        int r = idx >> 3, j = idx & 7;
        cp_async16(sQ + r * FROWB + j * 16, q16 + (bh * TT + t0 + r) * 64 + j * 8);
    }
    auto pref_kv = [&](int n) {
        const uint32_t sb = sKV + (uint32_t)(n % 3) * FSTAGE;
        const int j0 = n * 64;
        #pragma unroll
        for (int i = 0; i < 4; i++) {
            int idx = i * 256 + tid;
            int arr = idx >> 9, r = (idx >> 3) & 63, j = idx & 7;
            const __half* g = arr ? (vt16 + (bh * 64 + r) * TT + j0 + j * 8)
                                  : (k16 + (bh * TT + j0 + r) * 64 + j * 8);
            cp_async16(sb + arr * FK_TILE + r * FROWB + j * 16, g);
        }
    };
    pref_kv(0);
    asm volatile("cp.async.commit_group;" ::: "memory");
    pref_kv(1);
    asm volatile("cp.async.commit_group;" ::: "memory");

    const int wrow = t0 + warp * 16;
    const int gr = lane >> 2;
    const int qk = (lane & 3) * 2;
    const int row0 = wrow + gr;
    const int row1 = row0 + 8;

    uint32_t qa[4][4];
    float O[8][4];
    #pragma unroll
    for (int nt = 0; nt < 8; nt++)
        #pragma unroll
        for (int e = 0; e < 4; e++) O[nt][e] = 0.f;
    float mA = -1e30f, mB = -1e30f, lA = 0.f, lB = 0.f;

    const uint32_t bBaseOff = ((lane & 7) + ((lane >> 4) << 3)) * FROWB + (((lane >> 3) & 1) << 4);

    for (int n = 0; n < nkv; n++) {
        asm volatile("cp.async.wait_group 1;" ::: "memory");
        __syncthreads();

        if (n == 0) {
            const uint32_t qb = sQ + (warp * 16 + (lane & 15)) * FROWB + ((lane >> 4) << 4);
            #pragma unroll
            for (int ks = 0; ks < 4; ks++)
                ldsm_x4(qa[ks][0], qa[ks][1], qa[ks][2], qa[ks][3], qb + ks * 32);
        }

        const int j0 = n * 64;
        if (j0 <= wrow + 15) {
            const uint32_t sb = sKV + (uint32_t)(n % 3) * FSTAGE;
            float S[8][4];
            #pragma unroll
            for (int nt = 0; nt < 8; nt++)
                #pragma unroll
                for (int e = 0; e < 4; e++) S[nt][e] = 0.f;

            #pragma unroll
            for (int ks = 0; ks < 4; ks++) {
                uint32_t B0[8], B1[8];
                #pragma unroll
                for (int q2 = 0; q2 < 4; q2++) {
                    const uint32_t off = bBaseOff + q2 * (16 * FROWB) + ks * 32;
                    ldsm_x4(B0[q2*2], B1[q2*2], B0[q2*2+1], B1[q2*2+1], sb + off);
                }
                #pragma unroll
                for (int nt = 0; nt < 8; nt++) {
                    float* c = S[nt];
                    mma16816(c[0], c[1], c[2], c[3],
                             qa[ks][0], qa[ks][1], qa[ks][2], qa[ks][3], B0[nt], B1[nt]);
                }
            }

            if (j0 + 63 > wrow) {
                #pragma unroll
                for (int nt = 0; nt < 8; nt++) {
                    const int c0 = j0 + nt * 8 + qk;
                    if (c0 > row0)     S[nt][0] = -1e30f;
                    if (c0 + 1 > row0) S[nt][1] = -1e30f;
                    if (c0 > row1)     S[nt][2] = -1e30f;
                    if (c0 + 1 > row1) S[nt][3] = -1e30f;
                }
            }

            float tmA = -1e30f, tmB = -1e30f;
            #pragma unroll
            for (int nt = 0; nt < 8; nt++) {
                tmA = fmaxf(tmA, fmaxf(S[nt][0], S[nt][1]));
                tmB = fmaxf(tmB, fmaxf(S[nt][2], S[nt][3]));
            }
            tmA = fmaxf(tmA, __shfl_xor_sync(0xffffffffu, tmA, 1));
            tmA = fmaxf(tmA, __shfl_xor_sync(0xffffffffu, tmA, 2));
            tmB = fmaxf(tmB, __shfl_xor_sync(0xffffffffu, tmB, 1));
            tmB = fmaxf(tmB, __shfl_xor_sync(0xffffffffu, tmB, 2));

            if (__any_sync(0xffffffffu, (tmA > mA) || (tmB > mB))) {
                const float mnA = fmaxf(mA, tmA), mnB = fmaxf(mB, tmB);
                const float aA = exp2f(mA - mnA), aB = exp2f(mB - mnB);
                lA *= aA; lB *= aB;
                #pragma unroll
                for (int nt = 0; nt < 8; nt++) {
                    O[nt][0] *= aA; O[nt][1] *= aA;
                    O[nt][2] *= aB; O[nt][3] *= aB;
                }
                mA = mnA; mB = mnB;
            }

            float sumA = 0.f, sumB = 0.f;
            #pragma unroll
            for (int nt = 0; nt < 8; nt++) {
                S[nt][0] = exp2f(S[nt][0] - mA);
                S[nt][1] = exp2f(S[nt][1] - mA);
                S[nt][2] = exp2f(S[nt][2] - mB);
                S[nt][3] = exp2f(S[nt][3] - mB);
                sumA += S[nt][0] + S[nt][1];
                sumB += S[nt][2] + S[nt][3];
            }
            lA += sumA;
            lB += sumB;

            const uint32_t vb = sb + FK_TILE;
            #pragma unroll
            for (int ks = 0; ks < 4; ks++) {
                const int n0t = 2 * ks, n1t = 2 * ks + 1;
                uint32_t pa[4];
                pa[0] = pack_h16(S[n0t][0], S[n0t][1]);
                pa[1] = pack_h16(S[n0t][2], S[n0t][3]);
                pa[2] = pack_h16(S[n1t][0], S[n1t][1]);
                pa[3] = pack_h16(S[n1t][2], S[n1t][3]);
                uint32_t V0[8], V1[8];
                #pragma unroll
                for (int q2 = 0; q2 < 4; q2++) {
                    const uint32_t off = bBaseOff + q2 * (16 * FROWB) + ks * 32;
                    ldsm_x4(V0[q2*2], V1[q2*2], V0[q2*2+1], V1[q2*2+1], vb + off);
                }
                #pragma unroll
                for (int nt = 0; nt < 8; nt++) {
                    float* c = O[nt];
                    mma16816(c[0], c[1], c[2], c[3],
                             pa[0], pa[1], pa[2], pa[3], V0[nt], V1[nt]);
                }
            }
        }
        if (n + 2 < nkv) pref_kv(n + 2);
        asm volatile("cp.async.commit_group;" ::: "memory");
    }

    lA += __shfl_xor_sync(0xffffffffu, lA, 1);
    lA += __shfl_xor_sync(0xffffffffu, lA, 2);
    lB += __shfl_xor_sync(0xffffffffu, lB, 1);
    lB += __shfl_xor_sync(0xffffffffu, lB, 2);

    const float iA = 1.f / lA, iB = 1.f / lB;
    #pragma unroll
    for (int nt = 0; nt < 8; nt++) {
        const size_t d0 = (size_t)h * 64 + nt * 8 + qk;
        store_h2(y16, ((size_t)b * TT + row0) * CC + d0, O[nt][0] * iA, O[nt][1] * iA);
        store_h2(y16, ((size_t)b * TT + row1) * CC + d0, O[nt][2] * iB, O[nt][3] * iB);
    }
}

// ---------------- launch ---------------------------------------------------
extern "C" void kernel_launch(void* const* d_in, const int* in_sizes, int n_in,
                              void* d_out, int out_size)
{
    const float* x   = (const float*)d_in[0];
    const float* Wq  = (const float*)d_in[1];
    const float* Wkv = (const float*)d_in[2];
    const float* Wc  = (const float*)d_in[3];
    float* out = (float*)d_out;

    float *gc, *gs;
    __half *x16, *y16, *q16, *k16, *vt16, *wh, *wch;
    cudaGetSymbolAddress((void**)&gc, g_cos);
    cudaGetSymbolAddress((void**)&gs, g_sin);
    cudaGetSymbolAddress((void**)&x16, g_x16);
    cudaGetSymbolAddress((void**)&y16, g_y16);
    cudaGetSymbolAddress((void**)&q16, g_q16);
    cudaGetSymbolAddress((void**)&k16, g_k16);
    cudaGetSymbolAddress((void**)&vt16, g_vt16);
    cudaGetSymbolAddress((void**)&wh, g_wh);
    cudaGetSymbolAddress((void**)&wch, g_wch);

    cudaFuncSetAttribute(gemm_kernel_mma, cudaFuncAttributeMaxDynamicSharedMemorySize, SMEM_DYN);
    cudaFuncSetAttribute(flash_mma_kernel, cudaFuncAttributeMaxDynamicSharedMemorySize, FSMEM);

    // #0: x -> fp16
    {
        int n4 = MM * GK / 4;
        split_kernel<<<(n4 + 255) / 256, 256>>>((const float4*)x, (uint2*)x16, n4);
    }
    // #1: weight transposes (single fp16) + rope table
    transpose_split_all<<<dim3(128, GK / 32 + 1), dim3(32, 8)>>>(
        Wq, Wkv, Wc, wh, wch, gc, gs);

    // #2: fused QKV GEMM
    gemm_kernel_mma<<<dim3(3 * CC / 128, MM / 128), 256, SMEM_DYN>>>(
        x16, wh, nullptr, 3 * CC, 1, gc, gs, q16, k16, vt16);

    // #3: attention (ncu target)
    flash_mma_kernel<<<dim3(TT / 128, HH, BB), 256, FSMEM>>>(q16, k16, vt16, y16);

    // #4: out = y @ Wc
    gemm_kernel_mma<<<dim3(CC / 128, MM / 128), 256, SMEM_DYN>>>(
        y16, wch, out, CC, 0, nullptr, nullptr, nullptr, nullptr, nullptr);
}